// round 1
// baseline (speedup 1.0000x reference)
#include <cuda_runtime.h>
#include <math.h>

// Problem constants
#define S_LEN   2048
#define BATCH   2
#define DMODEL  512
#define NHEAD   8
#define DHEAD   64
#define NROWS   (S_LEN*BATCH)        // 4096
#define CHUNK   128
#define NCHUNK  (S_LEN/CHUNK)        // 16
#define NBH     (BATCH*NHEAD)        // 16
#define ATT_SCALE 0.125f             // 1/sqrt(64)
#define ATT_EPS   1e-5f
#define LN_EPS    1e-5f

// Scratch (static device globals — no allocation allowed)
__device__ float g_Q [NROWS*DMODEL];
__device__ float g_KV[NROWS*2*DMODEL];
__device__ float g_ckv[NBH*NCHUNK*DHEAD*DHEAD];
__device__ float g_cks[NBH*NCHUNK*DHEAD];
__device__ float g_pkv[NBH*NCHUNK*DHEAD*DHEAD];
__device__ float g_pks[NBH*NCHUNK*DHEAD];
__device__ float g_AV [NROWS*DMODEL];
__device__ float g_AO [NROWS*DMODEL];

__device__ __forceinline__ float elu1(float x) {
    return x > 0.f ? x + 1.f : expf(x);
}

// ---------------------------------------------------------------------------
// SGEMM: C[M,N] = A[M,K] @ B[K,N], fp32, 128x128 block tile, 8x8 per thread.
// MODE 0: plain   MODE 1: elu+1 on all outputs   MODE 2: elu+1 on cols < 512
// M,N multiples of 128; K multiple of 8.
// ---------------------------------------------------------------------------
template<int MODE>
__global__ __launch_bounds__(256, 2) void sgemm_kernel(
    const float* __restrict__ A, const float* __restrict__ B,
    float* __restrict__ C, int N, int K)
{
    __shared__ float As[8][128];   // transposed A tile: As[k][m]
    __shared__ float Bs[8][128];   // Bs[k][n]

    const int tid = threadIdx.x;
    const int tx  = tid & 15;      // 0..15 -> 8 output cols each
    const int ty  = tid >> 4;      // 0..15 -> 8 output rows each
    const int bm  = blockIdx.y, bn = blockIdx.x;

    const int arow = tid >> 1, acol = (tid & 1) << 2;   // A: 128 rows x 8 k
    const int brow = tid >> 5, bcol = (tid & 31) << 2;  // B: 8 k x 128 cols

    const float* Ap = A + (size_t)(bm*128 + arow)*K + acol;
    const float* Bp = B + (size_t)brow*N + bn*128 + bcol;

    float4 av = *(const float4*)Ap;
    float4 bv = *(const float4*)Bp;

    float acc[8][8];
    #pragma unroll
    for (int i = 0; i < 8; ++i)
        #pragma unroll
        for (int j = 0; j < 8; ++j) acc[i][j] = 0.f;

    const int nk = K >> 3;
    for (int kt = 0; kt < nk; ++kt) {
        As[acol+0][arow] = av.x;
        As[acol+1][arow] = av.y;
        As[acol+2][arow] = av.z;
        As[acol+3][arow] = av.w;
        *(float4*)&Bs[brow][bcol] = bv;
        __syncthreads();
        if (kt + 1 < nk) {
            av = *(const float4*)(Ap + (kt+1)*8);
            bv = *(const float4*)(Bp + (size_t)(kt+1)*8*N);
        }
        #pragma unroll
        for (int k = 0; k < 8; ++k) {
            float a[8], b[8];
            #pragma unroll
            for (int i = 0; i < 8; ++i) a[i] = As[k][ty*8 + i];
            #pragma unroll
            for (int j = 0; j < 8; ++j) b[j] = Bs[k][tx*8 + j];
            #pragma unroll
            for (int i = 0; i < 8; ++i)
                #pragma unroll
                for (int j = 0; j < 8; ++j)
                    acc[i][j] = fmaf(a[i], b[j], acc[i][j]);
        }
        __syncthreads();
    }

    const int crow0 = bm*128 + ty*8;
    const int ccol0 = bn*128 + tx*8;
    #pragma unroll
    for (int i = 0; i < 8; ++i) {
        float* Cp = C + (size_t)(crow0 + i)*N + ccol0;
        #pragma unroll
        for (int j = 0; j < 8; ++j) {
            float v = acc[i][j];
            if (MODE == 1) v = elu1(v);
            else if (MODE == 2) { if (ccol0 + j < 512) v = elu1(v); }
            Cp[j] = v;
        }
    }
}

// ---------------------------------------------------------------------------
// Per-chunk KV outer-product sums + K sums.
// grid (NCHUNK, NBH), 256 threads. Output ckv[bh][c][d*64+e], cks[bh][c][d].
// ---------------------------------------------------------------------------
__global__ __launch_bounds__(256) void chunk_kv_kernel(
    const float* __restrict__ KV, float* __restrict__ ckv, float* __restrict__ cks)
{
    const int c  = blockIdx.x, bh = blockIdx.y;
    const int b  = bh >> 3, hh = bh & 7;
    const int tid = threadIdx.x;

    __shared__ float sk[4][64], sv[4][64];

    const int d  = tid >> 2;            // 0..63 (outer-product row)
    const int e0 = (tid & 3) << 4;      // 16-wide column slice
    const int jj = tid >> 6, dd = tid & 63;  // load mapping

    float acc[16];
    #pragma unroll
    for (int r = 0; r < 16; ++r) acc[r] = 0.f;
    float ksum = 0.f;

    for (int j0 = 0; j0 < CHUNK; j0 += 4) {
        const int s = c*CHUNK + j0 + jj;
        const size_t base = ((size_t)(s*BATCH + b))*1024 + hh*64 + dd;
        const float kk_in = KV[base];
        const float vv_in = KV[base + 512];
        __syncthreads();
        sk[jj][dd] = kk_in;
        sv[jj][dd] = vv_in;
        __syncthreads();
        #pragma unroll
        for (int q = 0; q < 4; ++q) {
            const float kk = sk[q][d];
            #pragma unroll
            for (int r = 0; r < 16; ++r)
                acc[r] = fmaf(kk, sv[q][e0 + r], acc[r]);
        }
        if (tid < 64)
            ksum += sk[0][tid] + sk[1][tid] + sk[2][tid] + sk[3][tid];
    }

    float* outp = ckv + (((size_t)bh*NCHUNK + c) << 12) + d*64 + e0;
    #pragma unroll
    for (int r = 0; r < 16; ++r) outp[r] = acc[r];
    if (tid < 64) cks[(bh*NCHUNK + c)*64 + tid] = ksum;
}

// ---------------------------------------------------------------------------
// Exclusive prefix over chunks. grid NBH, 256 threads.
// ---------------------------------------------------------------------------
__global__ __launch_bounds__(256) void prefix_kernel(
    const float* __restrict__ ckv, const float* __restrict__ cks,
    float* __restrict__ pkv, float* __restrict__ pks)
{
    const int bh = blockIdx.x, tid = threadIdx.x;
    float acc[16];
    #pragma unroll
    for (int r = 0; r < 16; ++r) acc[r] = 0.f;

    for (int c = 0; c < NCHUNK; ++c) {
        const float* src = ckv + (((size_t)bh*NCHUNK + c) << 12);
        float*       dst = pkv + (((size_t)bh*NCHUNK + c) << 12);
        #pragma unroll
        for (int r = 0; r < 16; ++r) {
            const int idx = tid + r*256;
            dst[idx] = acc[r];
            acc[r]  += src[idx];
        }
    }
    if (tid < 64) {
        float a = 0.f;
        for (int c = 0; c < NCHUNK; ++c) {
            pks[(bh*NCHUNK + c)*64 + tid] = a;
            a += cks[(bh*NCHUNK + c)*64 + tid];
        }
    }
}

// ---------------------------------------------------------------------------
// Chunked linear attention. grid (NCHUNK, NBH), 256 threads, dynamic smem.
// ---------------------------------------------------------------------------
#define ATTN_SMEM_FLOATS (8192 /*Q*/ + 64*129 /*KT*/ + 8192 /*V*/ + 4096 /*St*/ \
                          + 64 /*kp*/ + 128 /*dloc*/ + 128*129 /*Ssc*/)
#define ATTN_SMEM_BYTES  (ATTN_SMEM_FLOATS * 4)

__global__ __launch_bounds__(256, 1) void attn_kernel(
    const float* __restrict__ Q, const float* __restrict__ KV,
    const float* __restrict__ pkv, const float* __restrict__ pks,
    float* __restrict__ AV)
{
    extern __shared__ float sm[];
    float* Qs   = sm;                 // [128][64]
    float* KsT  = Qs  + 8192;         // [64][129] (transposed, padded)
    float* Vs   = KsT + 64*129;       // [128][64]
    float* St   = Vs  + 8192;         // [64][64] state prefix
    float* kp   = St  + 4096;         // [64]
    float* dloc = kp  + 64;           // [128] 1/denominator
    float* Ssc  = dloc + 128;         // [128][129] masked scores (padded)

    const int c  = blockIdx.x, bh = blockIdx.y;
    const int b  = bh >> 3, hh = bh & 7;
    const int tid = threadIdx.x;

    // Loads
    for (int idx = tid; idx < CHUNK*DHEAD; idx += 256) {
        const int i = idx >> 6, k = idx & 63;
        const size_t row = (size_t)((c*CHUNK + i)*BATCH + b);
        Qs[idx]         = Q [row*512  + hh*64 + k];
        KsT[k*129 + i]  = KV[row*1024 + hh*64 + k];
        Vs[idx]         = KV[row*1024 + 512 + hh*64 + k];
    }
    for (int idx = tid; idx < 4096; idx += 256)
        St[idx] = pkv[(((size_t)bh*NCHUNK + c) << 12) + idx];
    if (tid < 64) kp[tid] = pks[(bh*NCHUNK + c)*64 + tid];
    __syncthreads();

    const int tr = tid >> 4, tc = tid & 15;

    // Stage 1: intra-chunk scores with causal mask (j <= i kept)
    {
        float acc[8][8];
        #pragma unroll
        for (int i = 0; i < 8; ++i)
            #pragma unroll
            for (int j = 0; j < 8; ++j) acc[i][j] = 0.f;
        #pragma unroll 4
        for (int k = 0; k < 64; ++k) {
            float qa[8], kb[8];
            #pragma unroll
            for (int ii = 0; ii < 8; ++ii) qa[ii] = Qs[(tr*8 + ii)*64 + k];
            #pragma unroll
            for (int jj = 0; jj < 8; ++jj) kb[jj] = KsT[k*129 + tc*8 + jj];
            #pragma unroll
            for (int ii = 0; ii < 8; ++ii)
                #pragma unroll
                for (int jj = 0; jj < 8; ++jj)
                    acc[ii][jj] = fmaf(qa[ii], kb[jj], acc[ii][jj]);
        }
        #pragma unroll
        for (int ii = 0; ii < 8; ++ii) {
            const int i = tr*8 + ii;
            #pragma unroll
            for (int jj = 0; jj < 8; ++jj) {
                const int j = tc*8 + jj;
                Ssc[i*129 + j] = (j <= i) ? acc[ii][jj] : 0.f;
            }
        }
    }
    __syncthreads();

    // Stage 2: denominators: rowsum of masked scores + q . kprefix
    {
        const int i = tid >> 1, half = tid & 1;
        float s0 = 0.f, s1 = 0.f, s2 = 0.f, s3 = 0.f;
        const int j0 = half*64;
        #pragma unroll 4
        for (int j = 0; j < 64; j += 4) {
            s0 += Ssc[i*129 + j0 + j];
            s1 += Ssc[i*129 + j0 + j + 1];
            s2 += Ssc[i*129 + j0 + j + 2];
            s3 += Ssc[i*129 + j0 + j + 3];
        }
        #pragma unroll 4
        for (int k = half*32; k < half*32 + 32; k += 4) {
            s0 = fmaf(Qs[i*64 + k],     kp[k],     s0);
            s1 = fmaf(Qs[i*64 + k + 1], kp[k + 1], s1);
            s2 = fmaf(Qs[i*64 + k + 2], kp[k + 2], s2);
            s3 = fmaf(Qs[i*64 + k + 3], kp[k + 3], s3);
        }
        float s = (s0 + s1) + (s2 + s3);
        s += __shfl_xor_sync(0xffffffffu, s, 1);
        if (half == 0) dloc[i] = 1.f / (s*ATT_SCALE + ATT_EPS);
    }
    __syncthreads();

    // Stage 3: O = (Q @ St) + (Ssc @ V), scaled & normalized
    {
        float acc[8][4];
        #pragma unroll
        for (int i = 0; i < 8; ++i)
            #pragma unroll
            for (int e = 0; e < 4; ++e) acc[i][e] = 0.f;

        #pragma unroll 4
        for (int k = 0; k < 64; ++k) {
            const float4 st = *(const float4*)&St[k*64 + tc*4];
            #pragma unroll
            for (int ii = 0; ii < 8; ++ii) {
                const float q = Qs[(tr*8 + ii)*64 + k];
                acc[ii][0] = fmaf(q, st.x, acc[ii][0]);
                acc[ii][1] = fmaf(q, st.y, acc[ii][1]);
                acc[ii][2] = fmaf(q, st.z, acc[ii][2]);
                acc[ii][3] = fmaf(q, st.w, acc[ii][3]);
            }
        }
        #pragma unroll 4
        for (int j = 0; j < 128; ++j) {
            const float4 vv = *(const float4*)&Vs[j*64 + tc*4];
            #pragma unroll
            for (int ii = 0; ii < 8; ++ii) {
                const float sc = Ssc[(tr*8 + ii)*129 + j];
                acc[ii][0] = fmaf(sc, vv.x, acc[ii][0]);
                acc[ii][1] = fmaf(sc, vv.y, acc[ii][1]);
                acc[ii][2] = fmaf(sc, vv.z, acc[ii][2]);
                acc[ii][3] = fmaf(sc, vv.w, acc[ii][3]);
            }
        }
        #pragma unroll
        for (int ii = 0; ii < 8; ++ii) {
            const int i = tr*8 + ii;
            const float scale = ATT_SCALE * dloc[i];
            const size_t row = (size_t)((c*CHUNK + i)*BATCH + b);
            float* outp = AV + row*512 + hh*64 + tc*4;
            #pragma unroll
            for (int e = 0; e < 4; ++e) outp[e] = acc[ii][e] * scale;
        }
    }
}

// ---------------------------------------------------------------------------
// LayerNorm(h + attn_out). One block per row (512 cols), 128 threads.
// ---------------------------------------------------------------------------
__global__ __launch_bounds__(128) void ln_kernel(
    const float* __restrict__ h, const float* __restrict__ ao,
    const float* __restrict__ gamma, const float* __restrict__ beta,
    float* __restrict__ out)
{
    const int row = blockIdx.x;
    const int tid = threadIdx.x;
    __shared__ float red[4];

    const float* hp = h  + (size_t)row*512;
    const float* ap = ao + (size_t)row*512;
    float x[4];
    #pragma unroll
    for (int r = 0; r < 4; ++r) x[r] = hp[tid + r*128] + ap[tid + r*128];

    float s = (x[0] + x[1]) + (x[2] + x[3]);
    #pragma unroll
    for (int o = 16; o > 0; o >>= 1) s += __shfl_xor_sync(0xffffffffu, s, o);
    if ((tid & 31) == 0) red[tid >> 5] = s;
    __syncthreads();
    const float mu = (red[0] + red[1] + red[2] + red[3]) * (1.f/512.f);
    __syncthreads();

    float v = 0.f;
    #pragma unroll
    for (int r = 0; r < 4; ++r) { const float d = x[r] - mu; v = fmaf(d, d, v); }
    #pragma unroll
    for (int o = 16; o > 0; o >>= 1) v += __shfl_xor_sync(0xffffffffu, v, o);
    if ((tid & 31) == 0) red[tid >> 5] = v;
    __syncthreads();
    const float var  = (red[0] + red[1] + red[2] + red[3]) * (1.f/512.f);
    const float rstd = rsqrtf(var + LN_EPS);

    #pragma unroll
    for (int r = 0; r < 4; ++r) {
        const int col = tid + r*128;
        out[(size_t)row*512 + col] = (x[r] - mu)*rstd*gamma[col] + beta[col];
    }
}

// ---------------------------------------------------------------------------
extern "C" void kernel_launch(void* const* d_in, const int* in_sizes, int n_in,
                              void* d_out, int out_size)
{
    (void)in_sizes; (void)n_in; (void)out_size;
    const float* h     = (const float*)d_in[0];
    const float* Wq    = (const float*)d_in[1];
    const float* Wkv   = (const float*)d_in[2];
    const float* Wo    = (const float*)d_in[3];
    const float* gamma = (const float*)d_in[4];
    const float* beta  = (const float*)d_in[5];
    // d_in[6] = attn_mask: known causal triu(k=1), not needed.
    float* out = (float*)d_out;

    float *Q, *KV, *ckv, *cks, *pkv, *pks, *AV, *AO;
    cudaGetSymbolAddress((void**)&Q,   g_Q);
    cudaGetSymbolAddress((void**)&KV,  g_KV);
    cudaGetSymbolAddress((void**)&ckv, g_ckv);
    cudaGetSymbolAddress((void**)&cks, g_cks);
    cudaGetSymbolAddress((void**)&pkv, g_pkv);
    cudaGetSymbolAddress((void**)&pks, g_pks);
    cudaGetSymbolAddress((void**)&AV,  g_AV);
    cudaGetSymbolAddress((void**)&AO,  g_AO);

    cudaFuncSetAttribute(attn_kernel,
                         cudaFuncAttributeMaxDynamicSharedMemorySize,
                         ATTN_SMEM_BYTES);

    // Q = elu1(h @ Wq)          [4096,512]
    sgemm_kernel<1><<<dim3(4, 32), 256>>>(h, Wq, Q, 512, 512);
    // KV = h @ Wkv; elu1 on K half (cols < 512)   [4096,1024]
    sgemm_kernel<2><<<dim3(8, 32), 256>>>(h, Wkv, KV, 1024, 512);
    // chunked linear attention
    chunk_kv_kernel<<<dim3(NCHUNK, NBH), 256>>>(KV, ckv, cks);
    prefix_kernel<<<NBH, 256>>>(ckv, cks, pkv, pks);
    attn_kernel<<<dim3(NCHUNK, NBH), 256, ATTN_SMEM_BYTES>>>(Q, KV, pkv, pks, AV);
    // attn_out = attn_vec @ Wo
    sgemm_kernel<0><<<dim3(4, 32), 256>>>(AV, Wo, AO, 512, 512);
    // out = LayerNorm(h + attn_out)
    ln_kernel<<<NROWS, 128>>>(h, AO, gamma, beta, out);
}

// round 3
// speedup vs baseline: 1.6894x; 1.6894x over previous
#include <cuda_runtime.h>
#include <cuda_bf16.h>
#include <cstdint>
#include <math.h>

// Problem constants
#define S_LEN   2048
#define BATCH   2
#define DMODEL  512
#define NHEAD   8
#define DHEAD   64
#define NROWS   (S_LEN*BATCH)        // 4096
#define CHUNK   128
#define NCHUNK  (S_LEN/CHUNK)        // 16
#define NBH     (BATCH*NHEAD)        // 16
#define ATT_SCALE 0.125f
#define ATT_EPS   1e-5f
#define LN_EPS    1e-5f

// ---------------------------------------------------------------------------
// PTX helpers — arch-agnostic only (sm_103 base target: NO tcgen05/TMEM)
// ---------------------------------------------------------------------------
__device__ __forceinline__ uint32_t smem_u32(const void* p) {
    uint32_t a;
    asm("{ .reg .u64 t; cvta.to.shared.u64 t, %1; cvt.u32.u64 %0, t; }"
        : "=r"(a) : "l"(p));
    return a;
}

#define LDSM4(r, addr) \
    asm volatile("ldmatrix.sync.aligned.m8n8.x4.shared.b16 {%0,%1,%2,%3}, [%4];" \
        : "=r"((r)[0]), "=r"((r)[1]), "=r"((r)[2]), "=r"((r)[3]) : "r"(addr))

#define MMA_BF16(d, a, b) \
    asm volatile("mma.sync.aligned.m16n8k16.row.col.f32.bf16.bf16.f32 " \
        "{%0,%1,%2,%3}, {%4,%5,%6,%7}, {%8,%9}, {%0,%1,%2,%3};" \
        : "+f"((d)[0]), "+f"((d)[1]), "+f"((d)[2]), "+f"((d)[3]) \
        : "r"((a)[0]), "r"((a)[1]), "r"((a)[2]), "r"((a)[3]), \
          "r"((b)[0]), "r"((b)[1]))

#define CP_ASYNC16(sdst, gsrc) \
    asm volatile("cp.async.cg.shared.global [%0], [%1], 16;" \
        :: "r"(sdst), "l"(gsrc) : "memory")
#define CP_COMMIT() asm volatile("cp.async.commit_group;" ::: "memory")
#define CP_WAIT1()  asm volatile("cp.async.wait_group 1;" ::: "memory")

// ---------------------------------------------------------------------------
// Scratch (static device globals — no allocation allowed)
// ---------------------------------------------------------------------------
__device__ float g_Q [NROWS*DMODEL];
__device__ float g_KV[NROWS*2*DMODEL];
__device__ float g_ckv[NBH*NCHUNK*DHEAD*DHEAD];
__device__ float g_cks[NBH*NCHUNK*DHEAD];
__device__ float g_pkv[NBH*NCHUNK*DHEAD*DHEAD];
__device__ float g_pks[NBH*NCHUNK*DHEAD];
__device__ float g_AO [NROWS*DMODEL];

__device__ __nv_bfloat16 g_hh [NROWS*DMODEL];
__device__ __nv_bfloat16 g_hl [NROWS*DMODEL];
__device__ __nv_bfloat16 g_AVh[NROWS*DMODEL];
__device__ __nv_bfloat16 g_AVl[NROWS*DMODEL];
__device__ __nv_bfloat16 g_Wqh [512*512];
__device__ __nv_bfloat16 g_Wql [512*512];
__device__ __nv_bfloat16 g_Wkvh[1024*512];
__device__ __nv_bfloat16 g_Wkvl[1024*512];
__device__ __nv_bfloat16 g_Woh [512*512];
__device__ __nv_bfloat16 g_Wol [512*512];

__device__ __forceinline__ float elu1(float x) {
    return x > 0.f ? x + 1.f : expf(x);
}

// ---------------------------------------------------------------------------
// Split fp32 -> bf16 hi/lo (elementwise, vectorized by 4)
// ---------------------------------------------------------------------------
__global__ __launch_bounds__(256) void split_kernel(
    const float* __restrict__ x, __nv_bfloat16* __restrict__ hi,
    __nv_bfloat16* __restrict__ lo, int n4)
{
    int i = blockIdx.x*256 + threadIdx.x;
    if (i >= n4) return;
    float4 v = ((const float4*)x)[i];
    __nv_bfloat16 h0 = __float2bfloat16_rn(v.x);
    __nv_bfloat16 h1 = __float2bfloat16_rn(v.y);
    __nv_bfloat16 h2 = __float2bfloat16_rn(v.z);
    __nv_bfloat16 h3 = __float2bfloat16_rn(v.w);
    __nv_bfloat162 ph0; ph0.x = h0; ph0.y = h1;
    __nv_bfloat162 ph1; ph1.x = h2; ph1.y = h3;
    __nv_bfloat162 pl0, pl1;
    pl0.x = __float2bfloat16_rn(v.x - __bfloat162float(h0));
    pl0.y = __float2bfloat16_rn(v.y - __bfloat162float(h1));
    pl1.x = __float2bfloat16_rn(v.z - __bfloat162float(h2));
    pl1.y = __float2bfloat16_rn(v.w - __bfloat162float(h3));
    ((__nv_bfloat162*)hi)[2*i]   = ph0;
    ((__nv_bfloat162*)hi)[2*i+1] = ph1;
    ((__nv_bfloat162*)lo)[2*i]   = pl0;
    ((__nv_bfloat162*)lo)[2*i+1] = pl1;
}

// ---------------------------------------------------------------------------
// Transpose + split weights: W[K,N] fp32 -> Th[N,K], Tl[N,K] bf16
// ---------------------------------------------------------------------------
__global__ __launch_bounds__(256) void wsplit_t_kernel(
    const float* __restrict__ W, __nv_bfloat16* __restrict__ Th,
    __nv_bfloat16* __restrict__ Tl, int K, int N)
{
    __shared__ float tile[32][33];
    const int n  = blockIdx.x*32 + threadIdx.x;
    const int k0 = blockIdx.y*32;
    #pragma unroll
    for (int r = 0; r < 32; r += 8)
        tile[threadIdx.y + r][threadIdx.x] = W[(size_t)(k0 + threadIdx.y + r)*N + n];
    __syncthreads();
    const int k  = k0 + threadIdx.x;
    const int nb = blockIdx.x*32;
    #pragma unroll
    for (int r = 0; r < 32; r += 8) {
        float v = tile[threadIdx.x][threadIdx.y + r];
        __nv_bfloat16 hv = __float2bfloat16_rn(v);
        Th[(size_t)(nb + threadIdx.y + r)*K + k] = hv;
        Tl[(size_t)(nb + threadIdx.y + r)*K + k] =
            __float2bfloat16_rn(v - __bfloat162float(hv));
    }
}

// ---------------------------------------------------------------------------
// mma.sync split-bf16 GEMM: C[M,N] = A[M,K] @ Wt^T  (Wt is [N,K] bf16 hi/lo)
// 128x128 CTA tile, 8 warps (2x4), warp tile 64x32, K-chunks of 32,
// cp.async double-buffered SMEM, ldmatrix fragments, fp32 accumulators.
// MODE 0: plain  1: elu+1 all  2: elu+1 where col<512
// ---------------------------------------------------------------------------
template<int MODE>
__global__ __launch_bounds__(256, 1) void gemm_mma(
    const __nv_bfloat16* __restrict__ Ah, const __nv_bfloat16* __restrict__ Al,
    const __nv_bfloat16* __restrict__ Bh, const __nv_bfloat16* __restrict__ Bl,
    float* __restrict__ C, int N, int K)
{
    extern __shared__ char smem[];
    constexpr uint32_t TILEB = 128*80;        // one 128x32 bf16 tile @ 80B rows
    constexpr uint32_t BUFB  = 4*TILEB;       // Ah,Al,Bh,Bl per buffer

    const int tid = threadIdx.x;
    const int wid = tid >> 5, lane = tid & 31;
    const int m0 = blockIdx.y*128, n0 = blockIdx.x*128;
    const int warp_m = wid >> 2, warp_n = wid & 3;
    const uint32_t smb = smem_u32(smem);

    // per-chunk global->smem issue (16B cp.async x4 tensors x2 halves)
    auto issue_chunk = [&](int kt, int buf) {
        const uint32_t sbase = smb + (uint32_t)buf*BUFB;
        #pragma unroll
        for (int half = 0; half < 2; ++half) {
            const int idx = tid + half*256;          // 0..511
            const int row = idx >> 2, c = idx & 3;
            const uint32_t soff = (uint32_t)(row*80 + c*16);
            const size_t ga = (size_t)(m0 + row)*K + (size_t)kt*32 + c*8;
            const size_t gb = (size_t)(n0 + row)*K + (size_t)kt*32 + c*8;
            CP_ASYNC16(sbase + soff,           Ah + ga);
            CP_ASYNC16(sbase + TILEB + soff,   Al + ga);
            CP_ASYNC16(sbase + 2*TILEB + soff, Bh + gb);
            CP_ASYNC16(sbase + 3*TILEB + soff, Bl + gb);
        }
        CP_COMMIT();
    };

    float d[4][4][4];
    #pragma unroll
    for (int mt = 0; mt < 4; ++mt)
        #pragma unroll
        for (int nt = 0; nt < 4; ++nt)
            #pragma unroll
            for (int e = 0; e < 4; ++e) d[mt][nt][e] = 0.f;

    const int NT = K >> 5;                    // 16
    issue_chunk(0, 0);
    issue_chunk(1, 1);

    for (int kt = 0; kt < NT; ++kt) {
        CP_WAIT1();
        __syncthreads();
        const uint32_t sA = smb + (uint32_t)(kt & 1)*BUFB;
        const uint32_t sB = sA + 2*TILEB;

        #pragma unroll
        for (int k16 = 0; k16 < 2; ++k16) {
            uint32_t ah[4][4], al[4][4];
            #pragma unroll
            for (int mt = 0; mt < 4; ++mt) {
                const uint32_t r = warp_m*64 + mt*16 + (lane & 15);
                const uint32_t addr = sA + r*80 + k16*32 + (lane >> 4)*16;
                LDSM4(ah[mt], addr);
                LDSM4(al[mt], addr + TILEB);
            }
            uint32_t bh[4][2], bl[4][2];
            #pragma unroll
            for (int p = 0; p < 2; ++p) {
                const uint32_t r = warp_n*32 + p*16 + (lane & 7) + ((lane & 16) >> 1);
                const uint32_t addr = sB + r*80 + k16*32 + (lane & 8)*2;
                uint32_t t[4];
                LDSM4(t, addr);
                bh[2*p][0] = t[0]; bh[2*p][1] = t[1];
                bh[2*p+1][0] = t[2]; bh[2*p+1][1] = t[3];
                LDSM4(t, addr + TILEB);
                bl[2*p][0] = t[0]; bl[2*p][1] = t[1];
                bl[2*p+1][0] = t[2]; bl[2*p+1][1] = t[3];
            }
            #pragma unroll
            for (int mt = 0; mt < 4; ++mt)
                #pragma unroll
                for (int nt = 0; nt < 4; ++nt) {
                    MMA_BF16(d[mt][nt], ah[mt], bh[nt]);
                    MMA_BF16(d[mt][nt], ah[mt], bl[nt]);
                    MMA_BF16(d[mt][nt], al[mt], bh[nt]);
                }
        }
        __syncthreads();
        if (kt + 2 < NT) issue_chunk(kt + 2, kt & 1);
    }

    // Epilogue
    const int mb = m0 + warp_m*64;
    const int nb = n0 + warp_n*32;
    const int qr = lane >> 2, qc = (lane & 3)*2;
    #pragma unroll
    for (int mt = 0; mt < 4; ++mt) {
        #pragma unroll
        for (int nt = 0; nt < 4; ++nt) {
            const int n = nb + nt*8 + qc;
            float v0 = d[mt][nt][0], v1 = d[mt][nt][1];
            float v2 = d[mt][nt][2], v3 = d[mt][nt][3];
            if ((MODE == 1) || (MODE == 2 && n < 512)) {
                v0 = elu1(v0); v1 = elu1(v1); v2 = elu1(v2); v3 = elu1(v3);
            }
            float2 p0; p0.x = v0; p0.y = v1;
            float2 p1; p1.x = v2; p1.y = v3;
            *(float2*)&C[(size_t)(mb + mt*16 + qr)*N + n]     = p0;
            *(float2*)&C[(size_t)(mb + mt*16 + qr + 8)*N + n] = p1;
        }
    }
}

// ---------------------------------------------------------------------------
// Per-chunk KV outer-product sums + K sums. grid (NCHUNK, NBH), 256 threads.
// ---------------------------------------------------------------------------
__global__ __launch_bounds__(256) void chunk_kv_kernel(
    const float* __restrict__ KV, float* __restrict__ ckv, float* __restrict__ cks)
{
    const int c  = blockIdx.x, bh = blockIdx.y;
    const int b  = bh >> 3, hh = bh & 7;
    const int tid = threadIdx.x;

    __shared__ float sk[4][64], sv[4][64];

    const int d  = tid >> 2;
    const int e0 = (tid & 3) << 4;
    const int jj = tid >> 6, dd = tid & 63;

    float acc[16];
    #pragma unroll
    for (int r = 0; r < 16; ++r) acc[r] = 0.f;
    float ksum = 0.f;

    for (int j0 = 0; j0 < CHUNK; j0 += 4) {
        const int s = c*CHUNK + j0 + jj;
        const size_t base = ((size_t)(s*BATCH + b))*1024 + hh*64 + dd;
        const float kk_in = KV[base];
        const float vv_in = KV[base + 512];
        __syncthreads();
        sk[jj][dd] = kk_in;
        sv[jj][dd] = vv_in;
        __syncthreads();
        #pragma unroll
        for (int q = 0; q < 4; ++q) {
            const float kk = sk[q][d];
            #pragma unroll
            for (int r = 0; r < 16; ++r)
                acc[r] = fmaf(kk, sv[q][e0 + r], acc[r]);
        }
        if (tid < 64)
            ksum += sk[0][tid] + sk[1][tid] + sk[2][tid] + sk[3][tid];
    }

    float* outp = ckv + (((size_t)bh*NCHUNK + c) << 12) + d*64 + e0;
    #pragma unroll
    for (int r = 0; r < 16; ++r) outp[r] = acc[r];
    if (tid < 64) cks[(bh*NCHUNK + c)*64 + tid] = ksum;
}

// ---------------------------------------------------------------------------
// Exclusive prefix over chunks — parallel. grid (NBH, 16), 256 threads.
// ---------------------------------------------------------------------------
__global__ __launch_bounds__(256) void prefix_kernel(
    const float* __restrict__ ckv, const float* __restrict__ cks,
    float* __restrict__ pkv, float* __restrict__ pks)
{
    const int bh  = blockIdx.x;
    const int idx = blockIdx.y*256 + threadIdx.x;      // 0..4095
    const size_t base = ((size_t)bh*NCHUNK) << 12;

    float v[NCHUNK];
    #pragma unroll
    for (int c = 0; c < NCHUNK; ++c) v[c] = ckv[base + ((size_t)c << 12) + idx];
    float acc = 0.f;
    #pragma unroll
    for (int c = 0; c < NCHUNK; ++c) {
        pkv[base + ((size_t)c << 12) + idx] = acc;
        acc += v[c];
    }
    if (blockIdx.y == 0 && threadIdx.x < 64) {
        const int t = threadIdx.x;
        float s[NCHUNK];
        #pragma unroll
        for (int c = 0; c < NCHUNK; ++c) s[c] = cks[(bh*NCHUNK + c)*64 + t];
        float a = 0.f;
        #pragma unroll
        for (int c = 0; c < NCHUNK; ++c) {
            pks[(bh*NCHUNK + c)*64 + t] = a;
            a += s[c];
        }
    }
}

// ---------------------------------------------------------------------------
// Chunked linear attention. grid (NCHUNK, NBH), 256 threads, dynamic smem.
// Writes AV directly as split bf16 hi/lo for the output-projection GEMM.
// ---------------------------------------------------------------------------
#define ATTN_SMEM_FLOATS (8192 + 64*129 + 8192 + 4096 + 64 + 128 + 128*129)
#define ATTN_SMEM_BYTES  (ATTN_SMEM_FLOATS * 4)

__global__ __launch_bounds__(256, 1) void attn_kernel(
    const float* __restrict__ Q, const float* __restrict__ KV,
    const float* __restrict__ pkv, const float* __restrict__ pks,
    __nv_bfloat16* __restrict__ AVh, __nv_bfloat16* __restrict__ AVl)
{
    extern __shared__ float sm[];
    float* Qs   = sm;
    float* KsT  = Qs  + 8192;
    float* Vs   = KsT + 64*129;
    float* St   = Vs  + 8192;
    float* kp   = St  + 4096;
    float* dloc = kp  + 64;
    float* Ssc  = dloc + 128;

    const int c  = blockIdx.x, bh = blockIdx.y;
    const int b  = bh >> 3, hh = bh & 7;
    const int tid = threadIdx.x;

    for (int idx = tid; idx < CHUNK*DHEAD; idx += 256) {
        const int i = idx >> 6, k = idx & 63;
        const size_t row = (size_t)((c*CHUNK + i)*BATCH + b);
        Qs[idx]         = Q [row*512  + hh*64 + k];
        KsT[k*129 + i]  = KV[row*1024 + hh*64 + k];
        Vs[idx]         = KV[row*1024 + 512 + hh*64 + k];
    }
    for (int idx = tid; idx < 4096; idx += 256)
        St[idx] = pkv[(((size_t)bh*NCHUNK + c) << 12) + idx];
    if (tid < 64) kp[tid] = pks[(bh*NCHUNK + c)*64 + tid];
    __syncthreads();

    const int tr = tid >> 4, tc = tid & 15;

    // Stage 1: intra-chunk masked scores
    {
        float acc[8][8];
        #pragma unroll
        for (int i = 0; i < 8; ++i)
            #pragma unroll
            for (int j = 0; j < 8; ++j) acc[i][j] = 0.f;
        #pragma unroll 4
        for (int k = 0; k < 64; ++k) {
            float qa[8], kb[8];
            #pragma unroll
            for (int ii = 0; ii < 8; ++ii) qa[ii] = Qs[(tr*8 + ii)*64 + k];
            #pragma unroll
            for (int jj = 0; jj < 8; ++jj) kb[jj] = KsT[k*129 + tc*8 + jj];
            #pragma unroll
            for (int ii = 0; ii < 8; ++ii)
                #pragma unroll
                for (int jj = 0; jj < 8; ++jj)
                    acc[ii][jj] = fmaf(qa[ii], kb[jj], acc[ii][jj]);
        }
        #pragma unroll
        for (int ii = 0; ii < 8; ++ii) {
            const int i = tr*8 + ii;
            #pragma unroll
            for (int jj = 0; jj < 8; ++jj) {
                const int j = tc*8 + jj;
                Ssc[i*129 + j] = (j <= i) ? acc[ii][jj] : 0.f;
            }
        }
    }
    __syncthreads();

    // Stage 2: denominators
    {
        const int i = tid >> 1, half = tid & 1;
        float s0 = 0.f, s1 = 0.f, s2 = 0.f, s3 = 0.f;
        const int j0 = half*64;
        #pragma unroll 4
        for (int j = 0; j < 64; j += 4) {
            s0 += Ssc[i*129 + j0 + j];
            s1 += Ssc[i*129 + j0 + j + 1];
            s2 += Ssc[i*129 + j0 + j + 2];
            s3 += Ssc[i*129 + j0 + j + 3];
        }
        #pragma unroll 4
        for (int k = half*32; k < half*32 + 32; k += 4) {
            s0 = fmaf(Qs[i*64 + k],     kp[k],     s0);
            s1 = fmaf(Qs[i*64 + k + 1], kp[k + 1], s1);
            s2 = fmaf(Qs[i*64 + k + 2], kp[k + 2], s2);
            s3 = fmaf(Qs[i*64 + k + 3], kp[k + 3], s3);
        }
        float s = (s0 + s1) + (s2 + s3);
        s += __shfl_xor_sync(0xffffffffu, s, 1);
        if (half == 0) dloc[i] = 1.f / (s*ATT_SCALE + ATT_EPS);
    }
    __syncthreads();

    // Stage 3: O = (Q @ St) + (Ssc @ V)
    {
        float acc[8][4];
        #pragma unroll
        for (int i = 0; i < 8; ++i)
            #pragma unroll
            for (int e = 0; e < 4; ++e) acc[i][e] = 0.f;

        #pragma unroll 4
        for (int k = 0; k < 64; ++k) {
            const float4 st = *(const float4*)&St[k*64 + tc*4];
            #pragma unroll
            for (int ii = 0; ii < 8; ++ii) {
                const float q = Qs[(tr*8 + ii)*64 + k];
                acc[ii][0] = fmaf(q, st.x, acc[ii][0]);
                acc[ii][1] = fmaf(q, st.y, acc[ii][1]);
                acc[ii][2] = fmaf(q, st.z, acc[ii][2]);
                acc[ii][3] = fmaf(q, st.w, acc[ii][3]);
            }
        }
        #pragma unroll 4
        for (int j = 0; j < 128; ++j) {
            const float4 vv = *(const float4*)&Vs[j*64 + tc*4];
            #pragma unroll
            for (int ii = 0; ii < 8; ++ii) {
                const float sc = Ssc[(tr*8 + ii)*129 + j];
                acc[ii][0] = fmaf(sc, vv.x, acc[ii][0]);
                acc[ii][1] = fmaf(sc, vv.y, acc[ii][1]);
                acc[ii][2] = fmaf(sc, vv.z, acc[ii][2]);
                acc[ii][3] = fmaf(sc, vv.w, acc[ii][3]);
            }
        }
        #pragma unroll
        for (int ii = 0; ii < 8; ++ii) {
            const int i = tr*8 + ii;
            const float scale = ATT_SCALE * dloc[i];
            const size_t row = (size_t)((c*CHUNK + i)*BATCH + b);
            const size_t off = row*512 + hh*64 + tc*4;
            float v0 = acc[ii][0]*scale, v1 = acc[ii][1]*scale;
            float v2 = acc[ii][2]*scale, v3 = acc[ii][3]*scale;
            __nv_bfloat16 h0 = __float2bfloat16_rn(v0);
            __nv_bfloat16 h1 = __float2bfloat16_rn(v1);
            __nv_bfloat16 h2 = __float2bfloat16_rn(v2);
            __nv_bfloat16 h3 = __float2bfloat16_rn(v3);
            __nv_bfloat162 ph0; ph0.x = h0; ph0.y = h1;
            __nv_bfloat162 ph1; ph1.x = h2; ph1.y = h3;
            __nv_bfloat162 pl0, pl1;
            pl0.x = __float2bfloat16_rn(v0 - __bfloat162float(h0));
            pl0.y = __float2bfloat16_rn(v1 - __bfloat162float(h1));
            pl1.x = __float2bfloat16_rn(v2 - __bfloat162float(h2));
            pl1.y = __float2bfloat16_rn(v3 - __bfloat162float(h3));
            *(__nv_bfloat162*)(AVh + off)     = ph0;
            *(__nv_bfloat162*)(AVh + off + 2) = ph1;
            *(__nv_bfloat162*)(AVl + off)     = pl0;
            *(__nv_bfloat162*)(AVl + off + 2) = pl1;
        }
    }
}

// ---------------------------------------------------------------------------
// LayerNorm(h + attn_out). One block per row (512 cols), 128 threads.
// ---------------------------------------------------------------------------
__global__ __launch_bounds__(128) void ln_kernel(
    const float* __restrict__ h, const float* __restrict__ ao,
    const float* __restrict__ gamma, const float* __restrict__ beta,
    float* __restrict__ out)
{
    const int row = blockIdx.x;
    const int tid = threadIdx.x;
    __shared__ float red[4];

    const float* hp = h  + (size_t)row*512;
    const float* ap = ao + (size_t)row*512;
    float x[4];
    #pragma unroll
    for (int r = 0; r < 4; ++r) x[r] = hp[tid + r*128] + ap[tid + r*128];

    float s = (x[0] + x[1]) + (x[2] + x[3]);
    #pragma unroll
    for (int o = 16; o > 0; o >>= 1) s += __shfl_xor_sync(0xffffffffu, s, o);
    if ((tid & 31) == 0) red[tid >> 5] = s;
    __syncthreads();
    const float mu = (red[0] + red[1] + red[2] + red[3]) * (1.f/512.f);
    __syncthreads();

    float v = 0.f;
    #pragma unroll
    for (int r = 0; r < 4; ++r) { const float d = x[r] - mu; v = fmaf(d, d, v); }
    #pragma unroll
    for (int o = 16; o > 0; o >>= 1) v += __shfl_xor_sync(0xffffffffu, v, o);
    if ((tid & 31) == 0) red[tid >> 5] = v;
    __syncthreads();
    const float var  = (red[0] + red[1] + red[2] + red[3]) * (1.f/512.f);
    const float rstd = rsqrtf(var + LN_EPS);

    #pragma unroll
    for (int r = 0; r < 4; ++r) {
        const int col = tid + r*128;
        out[(size_t)row*512 + col] = (x[r] - mu)*rstd*gamma[col] + beta[col];
    }
}

// ---------------------------------------------------------------------------
extern "C" void kernel_launch(void* const* d_in, const int* in_sizes, int n_in,
                              void* d_out, int out_size)
{
    (void)in_sizes; (void)n_in; (void)out_size;
    const float* h     = (const float*)d_in[0];
    const float* Wq    = (const float*)d_in[1];
    const float* Wkv   = (const float*)d_in[2];
    const float* Wo    = (const float*)d_in[3];
    const float* gamma = (const float*)d_in[4];
    const float* beta  = (const float*)d_in[5];
    float* out = (float*)d_out;

    float *Q, *KV, *ckv, *cks, *pkv, *pks, *AO;
    __nv_bfloat16 *hh, *hl, *AVh, *AVl, *Wqh, *Wql, *Wkvh, *Wkvl, *Woh, *Wol;
    cudaGetSymbolAddress((void**)&Q,    g_Q);
    cudaGetSymbolAddress((void**)&KV,   g_KV);
    cudaGetSymbolAddress((void**)&ckv,  g_ckv);
    cudaGetSymbolAddress((void**)&cks,  g_cks);
    cudaGetSymbolAddress((void**)&pkv,  g_pkv);
    cudaGetSymbolAddress((void**)&pks,  g_pks);
    cudaGetSymbolAddress((void**)&AO,   g_AO);
    cudaGetSymbolAddress((void**)&hh,   g_hh);
    cudaGetSymbolAddress((void**)&hl,   g_hl);
    cudaGetSymbolAddress((void**)&AVh,  g_AVh);
    cudaGetSymbolAddress((void**)&AVl,  g_AVl);
    cudaGetSymbolAddress((void**)&Wqh,  g_Wqh);
    cudaGetSymbolAddress((void**)&Wql,  g_Wql);
    cudaGetSymbolAddress((void**)&Wkvh, g_Wkvh);
    cudaGetSymbolAddress((void**)&Wkvl, g_Wkvl);
    cudaGetSymbolAddress((void**)&Woh,  g_Woh);
    cudaGetSymbolAddress((void**)&Wol,  g_Wol);

    constexpr int GEMM_SMEM = 2 * 4 * 128 * 80;   // 81920 bytes

    cudaFuncSetAttribute(gemm_mma<0>, cudaFuncAttributeMaxDynamicSharedMemorySize, GEMM_SMEM);
    cudaFuncSetAttribute(gemm_mma<1>, cudaFuncAttributeMaxDynamicSharedMemorySize, GEMM_SMEM);
    cudaFuncSetAttribute(gemm_mma<2>, cudaFuncAttributeMaxDynamicSharedMemorySize, GEMM_SMEM);
    cudaFuncSetAttribute(attn_kernel, cudaFuncAttributeMaxDynamicSharedMemorySize, ATTN_SMEM_BYTES);

    // 0. split inputs / weights to bf16 hi/lo (weights also transposed to [N,K])
    split_kernel<<<(NROWS*DMODEL/4 + 255)/256, 256>>>(h, hh, hl, NROWS*DMODEL/4);
    wsplit_t_kernel<<<dim3(16, 16), dim3(32, 8)>>>(Wq,  Wqh,  Wql,  512, 512);
    wsplit_t_kernel<<<dim3(32, 16), dim3(32, 8)>>>(Wkv, Wkvh, Wkvl, 512, 1024);
    wsplit_t_kernel<<<dim3(16, 16), dim3(32, 8)>>>(Wo,  Woh,  Wol,  512, 512);

    // 1. Q = elu1(h @ Wq)
    gemm_mma<1><<<dim3(4, 32), 256, GEMM_SMEM>>>(hh, hl, Wqh, Wql, Q, 512, 512);
    // 2. KV = h @ Wkv, elu1 on cols < 512
    gemm_mma<2><<<dim3(8, 32), 256, GEMM_SMEM>>>(hh, hl, Wkvh, Wkvl, KV, 1024, 512);

    // 3. chunked linear attention
    chunk_kv_kernel<<<dim3(NCHUNK, NBH), 256>>>(KV, ckv, cks);
    prefix_kernel<<<dim3(NBH, 16), 256>>>(ckv, cks, pkv, pks);
    attn_kernel<<<dim3(NCHUNK, NBH), 256, ATTN_SMEM_BYTES>>>(Q, KV, pkv, pks, AVh, AVl);

    // 4. attn_out = attn_vec @ Wo
    gemm_mma<0><<<dim3(4, 32), 256, GEMM_SMEM>>>(AVh, AVl, Woh, Wol, AO, 512, 512);

    // 5. out = LayerNorm(h + attn_out)
    ln_kernel<<<NROWS, 128>>>(h, AO, gamma, beta, out);
}

// round 4
// speedup vs baseline: 1.9680x; 1.1649x over previous
#include <cuda_runtime.h>
#include <cuda_bf16.h>
#include <cstdint>
#include <math.h>

// Problem constants
#define S_LEN   2048
#define BATCH   2
#define DMODEL  512
#define NHEAD   8
#define DHEAD   64
#define NROWS   (S_LEN*BATCH)        // 4096
#define CHUNK   128
#define NCHUNK  (S_LEN/CHUNK)        // 16
#define NBH     (BATCH*NHEAD)        // 16
#define ATT_SCALE 0.125f
#define ATT_EPS   1e-5f
#define LN_EPS    1e-5f

// ---------------------------------------------------------------------------
// PTX helpers — arch-agnostic (plain sm_103 target: no tcgen05)
// ---------------------------------------------------------------------------
__device__ __forceinline__ uint32_t smem_u32(const void* p) {
    uint32_t a;
    asm("{ .reg .u64 t; cvta.to.shared.u64 t, %1; cvt.u32.u64 %0, t; }"
        : "=r"(a) : "l"(p));
    return a;
}

#define LDSM4(r, addr) \
    asm volatile("ldmatrix.sync.aligned.m8n8.x4.shared.b16 {%0,%1,%2,%3}, [%4];" \
        : "=r"((r)[0]), "=r"((r)[1]), "=r"((r)[2]), "=r"((r)[3]) : "r"(addr))

#define LDSM4T(r, addr) \
    asm volatile("ldmatrix.sync.aligned.m8n8.x4.trans.shared.b16 {%0,%1,%2,%3}, [%4];" \
        : "=r"((r)[0]), "=r"((r)[1]), "=r"((r)[2]), "=r"((r)[3]) : "r"(addr))

#define MMA_BF16(d, a, b) \
    asm volatile("mma.sync.aligned.m16n8k16.row.col.f32.bf16.bf16.f32 " \
        "{%0,%1,%2,%3}, {%4,%5,%6,%7}, {%8,%9}, {%0,%1,%2,%3};" \
        : "+f"((d)[0]), "+f"((d)[1]), "+f"((d)[2]), "+f"((d)[3]) \
        : "r"((a)[0]), "r"((a)[1]), "r"((a)[2]), "r"((a)[3]), \
          "r"((b)[0]), "r"((b)[1]))

#define CP_ASYNC16(sdst, gsrc) \
    asm volatile("cp.async.cg.shared.global [%0], [%1], 16;" \
        :: "r"(sdst), "l"(gsrc) : "memory")
#define CP_COMMIT() asm volatile("cp.async.commit_group;" ::: "memory")
#define CP_WAIT1()  asm volatile("cp.async.wait_group 1;" ::: "memory")

// ---------------------------------------------------------------------------
// Scratch (static device globals — no allocation allowed)
// ---------------------------------------------------------------------------
__device__ __nv_bfloat16 g_hh [NROWS*DMODEL];
__device__ __nv_bfloat16 g_hl [NROWS*DMODEL];
__device__ __nv_bfloat16 g_Wqh [512*512];
__device__ __nv_bfloat16 g_Wql [512*512];
__device__ __nv_bfloat16 g_Wkvh[512*1024];
__device__ __nv_bfloat16 g_Wkvl[512*1024];
__device__ __nv_bfloat16 g_Woh [512*512];
__device__ __nv_bfloat16 g_Wol [512*512];

__device__ __nv_bfloat16 g_Qh[NROWS*DMODEL];
__device__ __nv_bfloat16 g_Ql[NROWS*DMODEL];
__device__ __nv_bfloat16 g_Kh[NROWS*DMODEL];
__device__ __nv_bfloat16 g_Kl[NROWS*DMODEL];
__device__ __nv_bfloat16 g_Vh[NROWS*DMODEL];
__device__ __nv_bfloat16 g_Vl[NROWS*DMODEL];

__device__ float g_ckv[NBH*NCHUNK*DHEAD*DHEAD];
__device__ float g_cks[NBH*NCHUNK*DHEAD];
__device__ __nv_bfloat16 g_pkvh[NBH*NCHUNK*DHEAD*DHEAD];
__device__ __nv_bfloat16 g_pkvl[NBH*NCHUNK*DHEAD*DHEAD];
__device__ float g_pks[NBH*NCHUNK*DHEAD];

__device__ __nv_bfloat16 g_AVh[NROWS*DMODEL];
__device__ __nv_bfloat16 g_AVl[NROWS*DMODEL];
__device__ float g_AO [NROWS*DMODEL];

__device__ __forceinline__ float elu1(float x) {
    return x > 0.f ? x + 1.f : expf(x);
}
__device__ __forceinline__ void split_bf16(float v, __nv_bfloat16& h, __nv_bfloat16& l) {
    h = __float2bfloat16_rn(v);
    l = __float2bfloat16_rn(v - __bfloat162float(h));
}

// ---------------------------------------------------------------------------
// Split fp32 -> bf16 hi/lo (elementwise, no transpose)
// ---------------------------------------------------------------------------
__global__ __launch_bounds__(256) void split_kernel(
    const float* __restrict__ x, __nv_bfloat16* __restrict__ hi,
    __nv_bfloat16* __restrict__ lo, int n4)
{
    int i = blockIdx.x*256 + threadIdx.x;
    if (i >= n4) return;
    float4 v = ((const float4*)x)[i];
    __nv_bfloat16 h0, h1, h2, h3, l0, l1, l2, l3;
    split_bf16(v.x, h0, l0); split_bf16(v.y, h1, l1);
    split_bf16(v.z, h2, l2); split_bf16(v.w, h3, l3);
    __nv_bfloat162 ph0; ph0.x = h0; ph0.y = h1;
    __nv_bfloat162 ph1; ph1.x = h2; ph1.y = h3;
    __nv_bfloat162 pl0; pl0.x = l0; pl0.y = l1;
    __nv_bfloat162 pl1; pl1.x = l2; pl1.y = l3;
    ((__nv_bfloat162*)hi)[2*i]   = ph0;
    ((__nv_bfloat162*)hi)[2*i+1] = ph1;
    ((__nv_bfloat162*)lo)[2*i]   = pl0;
    ((__nv_bfloat162*)lo)[2*i+1] = pl1;
}

// ---------------------------------------------------------------------------
// mma.sync split-bf16 GEMM: C[M,N] = A[M,K] @ W[K,N]   (W row-major [K,N])
// A hi/lo bf16 [M,K]; B via ldmatrix.trans. 128x128 CTA tile, 8 warps (2x4),
// warp tile 64x32, K-chunks of 32, cp.async double-buffered, fp32 accum.
// MODE 0: fp32 out to C
// MODE 1: elu+1, split -> (D1h,D1l)                     [Q path]
// MODE 2: n0<512: elu+1 split -> D1 (K); else split -> D2 (V, col-512)
// ---------------------------------------------------------------------------
template<int MODE>
__global__ __launch_bounds__(256, 1) void gemm_mma(
    const __nv_bfloat16* __restrict__ Ah, const __nv_bfloat16* __restrict__ Al,
    const __nv_bfloat16* __restrict__ Bh, const __nv_bfloat16* __restrict__ Bl,
    float* __restrict__ C,
    __nv_bfloat16* __restrict__ D1h, __nv_bfloat16* __restrict__ D1l,
    __nv_bfloat16* __restrict__ D2h, __nv_bfloat16* __restrict__ D2l,
    int N, int K)
{
    extern __shared__ char smem[];
    constexpr uint32_t TILEA = 128*80;     // 128 m x 32 k bf16, 80B pitch
    constexpr uint32_t TILEB = 32*272;     // 32 k x 128 n bf16, 272B pitch
    constexpr uint32_t BUFB  = 2*TILEA + 2*TILEB;

    const int tid = threadIdx.x;
    const int wid = tid >> 5, lane = tid & 31;
    const int m0 = blockIdx.y*128, n0 = blockIdx.x*128;
    const int warp_m = wid >> 2, warp_n = wid & 3;
    const uint32_t smb = smem_u32(smem);

    auto issue_chunk = [&](int kt, int buf) {
        const uint32_t sbase = smb + (uint32_t)buf*BUFB;
        #pragma unroll
        for (int half = 0; half < 2; ++half) {
            const int idx = tid + half*256;            // 0..511
            // A: row-major [M,K], 64B per (row, chunk)
            const int ar = idx >> 2, ac = idx & 3;
            const uint32_t asoff = (uint32_t)(ar*80 + ac*16);
            const size_t ga = (size_t)(m0 + ar)*K + (size_t)kt*32 + ac*8;
            CP_ASYNC16(sbase + asoff,         Ah + ga);
            CP_ASYNC16(sbase + TILEA + asoff, Al + ga);
            // B: row-major [K,N], 256B per k-row
            const int br = idx >> 4, bc = idx & 15;
            const uint32_t bsoff = (uint32_t)(br*272 + bc*16);
            const size_t gb = (size_t)(kt*32 + br)*N + n0 + bc*8;
            CP_ASYNC16(sbase + 2*TILEA + bsoff,         Bh + gb);
            CP_ASYNC16(sbase + 2*TILEA + TILEB + bsoff, Bl + gb);
        }
        CP_COMMIT();
    };

    float d[4][4][4];
    #pragma unroll
    for (int mt = 0; mt < 4; ++mt)
        #pragma unroll
        for (int nt = 0; nt < 4; ++nt)
            #pragma unroll
            for (int e = 0; e < 4; ++e) d[mt][nt][e] = 0.f;

    const int NT = K >> 5;
    issue_chunk(0, 0);
    issue_chunk(1, 1);

    for (int kt = 0; kt < NT; ++kt) {
        CP_WAIT1();
        __syncthreads();
        const uint32_t sA = smb + (uint32_t)(kt & 1)*BUFB;
        const uint32_t sB = sA + 2*TILEA;

        #pragma unroll
        for (int k16 = 0; k16 < 2; ++k16) {
            uint32_t ah[4][4], al[4][4];
            #pragma unroll
            for (int mt = 0; mt < 4; ++mt) {
                const uint32_t r = warp_m*64 + mt*16 + (lane & 15);
                const uint32_t addr = sA + r*80 + k16*32 + (lane >> 4)*16;
                LDSM4(ah[mt], addr);
                LDSM4(al[mt], addr + TILEA);
            }
            uint32_t bh[4][2], bl[4][2];
            #pragma unroll
            for (int p = 0; p < 2; ++p) {
                // trans-ldmatrix on row-major [K,N]: lane reads k-row, n-col
                const uint32_t addr = sB + (k16*16 + (lane & 15))*272
                                    + (warp_n*32 + p*16 + (lane >> 4)*8)*2;
                uint32_t t[4];
                LDSM4T(t, addr);
                bh[2*p][0] = t[0]; bh[2*p][1] = t[1];
                bh[2*p+1][0] = t[2]; bh[2*p+1][1] = t[3];
                LDSM4T(t, addr + TILEB);
                bl[2*p][0] = t[0]; bl[2*p][1] = t[1];
                bl[2*p+1][0] = t[2]; bl[2*p+1][1] = t[3];
            }
            #pragma unroll
            for (int mt = 0; mt < 4; ++mt)
                #pragma unroll
                for (int nt = 0; nt < 4; ++nt) {
                    MMA_BF16(d[mt][nt], ah[mt], bh[nt]);
                    MMA_BF16(d[mt][nt], ah[mt], bl[nt]);
                    MMA_BF16(d[mt][nt], al[mt], bh[nt]);
                }
        }
        __syncthreads();
        if (kt + 2 < NT) issue_chunk(kt + 2, kt & 1);
    }

    // Epilogue
    const int mb = m0 + warp_m*64;
    const int qr = lane >> 2, qc = (lane & 3)*2;
    #pragma unroll
    for (int mt = 0; mt < 4; ++mt) {
        const int r0 = mb + mt*16 + qr, r1 = r0 + 8;
        #pragma unroll
        for (int nt = 0; nt < 4; ++nt) {
            const int nl = warp_n*32 + nt*8 + qc;     // 0..127 in tile
            const int n  = n0 + nl;
            float v0 = d[mt][nt][0], v1 = d[mt][nt][1];
            float v2 = d[mt][nt][2], v3 = d[mt][nt][3];
            if (MODE == 0) {
                float2 p0; p0.x = v0; p0.y = v1;
                float2 p1; p1.x = v2; p1.y = v3;
                *(float2*)&C[(size_t)r0*N + n] = p0;
                *(float2*)&C[(size_t)r1*N + n] = p1;
            } else {
                __nv_bfloat16* dh; __nv_bfloat16* dl; int col;
                bool do_elu;
                if (MODE == 1) { dh = D1h; dl = D1l; col = n; do_elu = true; }
                else {
                    if (n0 < 512) { dh = D1h; dl = D1l; col = n;      do_elu = true; }
                    else          { dh = D2h; dl = D2l; col = n - 512; do_elu = false; }
                }
                if (do_elu) { v0 = elu1(v0); v1 = elu1(v1); v2 = elu1(v2); v3 = elu1(v3); }
                __nv_bfloat16 h0,h1,h2,h3,l0,l1,l2,l3;
                split_bf16(v0,h0,l0); split_bf16(v1,h1,l1);
                split_bf16(v2,h2,l2); split_bf16(v3,h3,l3);
                __nv_bfloat162 ph0; ph0.x=h0; ph0.y=h1;
                __nv_bfloat162 ph1; ph1.x=h2; ph1.y=h3;
                __nv_bfloat162 pl0; pl0.x=l0; pl0.y=l1;
                __nv_bfloat162 pl1; pl1.x=l2; pl1.y=l3;
                *(__nv_bfloat162*)&dh[(size_t)r0*512 + col] = ph0;
                *(__nv_bfloat162*)&dh[(size_t)r1*512 + col] = ph1;
                *(__nv_bfloat162*)&dl[(size_t)r0*512 + col] = pl0;
                *(__nv_bfloat162*)&dl[(size_t)r1*512 + col] = pl1;
            }
        }
    }
}

// ---------------------------------------------------------------------------
// Per-chunk KV outer-product sums + K sums. grid (NCHUNK, NBH), 256 threads.
// K,V read as bf16 hi/lo, reconstructed fp32.
// ---------------------------------------------------------------------------
__global__ __launch_bounds__(256) void chunk_kv_kernel(
    const __nv_bfloat16* __restrict__ Kh, const __nv_bfloat16* __restrict__ Kl,
    const __nv_bfloat16* __restrict__ Vh, const __nv_bfloat16* __restrict__ Vl,
    float* __restrict__ ckv, float* __restrict__ cks)
{
    const int c  = blockIdx.x, bh = blockIdx.y;
    const int b  = bh >> 3, hh = bh & 7;
    const int tid = threadIdx.x;

    __shared__ float sk[4][64], sv[4][64];

    const int d  = tid >> 2;
    const int e0 = (tid & 3) << 4;
    const int jj = tid >> 6, dd = tid & 63;

    float acc[16];
    #pragma unroll
    for (int r = 0; r < 16; ++r) acc[r] = 0.f;
    float ksum = 0.f;

    for (int j0 = 0; j0 < CHUNK; j0 += 4) {
        const int s = c*CHUNK + j0 + jj;
        const size_t base = ((size_t)(s*BATCH + b))*512 + hh*64 + dd;
        const float kk_in = __bfloat162float(Kh[base]) + __bfloat162float(Kl[base]);
        const float vv_in = __bfloat162float(Vh[base]) + __bfloat162float(Vl[base]);
        __syncthreads();
        sk[jj][dd] = kk_in;
        sv[jj][dd] = vv_in;
        __syncthreads();
        #pragma unroll
        for (int q = 0; q < 4; ++q) {
            const float kk = sk[q][d];
            #pragma unroll
            for (int r = 0; r < 16; ++r)
                acc[r] = fmaf(kk, sv[q][e0 + r], acc[r]);
        }
        if (tid < 64)
            ksum += sk[0][tid] + sk[1][tid] + sk[2][tid] + sk[3][tid];
    }

    float* outp = ckv + (((size_t)bh*NCHUNK + c) << 12) + d*64 + e0;
    #pragma unroll
    for (int r = 0; r < 16; ++r) outp[r] = acc[r];
    if (tid < 64) cks[(bh*NCHUNK + c)*64 + tid] = ksum;
}

// ---------------------------------------------------------------------------
// Exclusive prefix over chunks — outputs St as bf16 hi/lo. grid (NBH,16).
// ---------------------------------------------------------------------------
__global__ __launch_bounds__(256) void prefix_kernel(
    const float* __restrict__ ckv, const float* __restrict__ cks,
    __nv_bfloat16* __restrict__ pkvh, __nv_bfloat16* __restrict__ pkvl,
    float* __restrict__ pks)
{
    const int bh  = blockIdx.x;
    const int idx = blockIdx.y*256 + threadIdx.x;      // 0..4095
    const size_t base = ((size_t)bh*NCHUNK) << 12;

    float v[NCHUNK];
    #pragma unroll
    for (int c = 0; c < NCHUNK; ++c) v[c] = ckv[base + ((size_t)c << 12) + idx];
    float acc = 0.f;
    #pragma unroll
    for (int c = 0; c < NCHUNK; ++c) {
        __nv_bfloat16 ph, pl;
        split_bf16(acc, ph, pl);
        pkvh[base + ((size_t)c << 12) + idx] = ph;
        pkvl[base + ((size_t)c << 12) + idx] = pl;
        acc += v[c];
    }
    if (blockIdx.y == 0 && threadIdx.x < 64) {
        const int t = threadIdx.x;
        float s[NCHUNK];
        #pragma unroll
        for (int c = 0; c < NCHUNK; ++c) s[c] = cks[(bh*NCHUNK + c)*64 + t];
        float a = 0.f;
        #pragma unroll
        for (int c = 0; c < NCHUNK; ++c) {
            pks[(bh*NCHUNK + c)*64 + t] = a;
            a += s[c];
        }
    }
}

// ---------------------------------------------------------------------------
// Tensor-core chunked linear attention. grid (NCHUNK, NBH), 256 threads.
// All matmuls via split-bf16 mma.sync (3 terms, fp32 accumulate).
// ---------------------------------------------------------------------------
// SMEM layout (bytes):
#define A_QH   0u
#define A_QL   18432u
#define A_KH   36864u
#define A_KL   55296u
#define A_VH   73728u
#define A_VL   92160u
#define A_STH  110592u
#define A_STL  119808u
#define A_SCH  129024u
#define A_SCL  163840u
#define A_KP   198656u
#define A_DLOC 198912u
#define ATTN_SMEM_BYTES 199424

__global__ __launch_bounds__(256, 1) void attn_kernel(
    const __nv_bfloat16* __restrict__ Qh, const __nv_bfloat16* __restrict__ Ql,
    const __nv_bfloat16* __restrict__ Kh, const __nv_bfloat16* __restrict__ Kl,
    const __nv_bfloat16* __restrict__ Vh, const __nv_bfloat16* __restrict__ Vl,
    const __nv_bfloat16* __restrict__ pkvh, const __nv_bfloat16* __restrict__ pkvl,
    const float* __restrict__ pks,
    __nv_bfloat16* __restrict__ AVh, __nv_bfloat16* __restrict__ AVl)
{
    extern __shared__ char sm[];
    const uint32_t smb = smem_u32(sm);

    const int c  = blockIdx.x, bh = blockIdx.y;
    const int b  = bh >> 3, hh = bh & 7;
    const int tid = threadIdx.x;
    const int wid = tid >> 5, lane = tid & 31;
    const int warp_m = wid >> 2, warp_n = wid & 3;

    // ---- loads: Q/K/V tiles [128 rows][64 k] bf16, pitch 144B ----
    {
        const __nv_bfloat162* Qh2 = (const __nv_bfloat162*)Qh;
        const __nv_bfloat162* Ql2 = (const __nv_bfloat162*)Ql;
        const __nv_bfloat162* Kh2 = (const __nv_bfloat162*)Kh;
        const __nv_bfloat162* Kl2 = (const __nv_bfloat162*)Kl;
        const __nv_bfloat162* Vh2 = (const __nv_bfloat162*)Vh;
        const __nv_bfloat162* Vl2 = (const __nv_bfloat162*)Vl;
        #pragma unroll
        for (int t = 0; t < 16; ++t) {
            const int u = tid + t*256;                 // 0..4095
            const int row = u >> 5, c2 = u & 31;
            const size_t grow = (size_t)((c*CHUNK + row)*BATCH + b);
            const size_t g = grow*256 + hh*32 + c2;
            const uint32_t so = row*144 + c2*4;
            *(__nv_bfloat162*)(sm + A_QH + so) = Qh2[g];
            *(__nv_bfloat162*)(sm + A_QL + so) = Ql2[g];
            *(__nv_bfloat162*)(sm + A_KH + so) = Kh2[g];
            *(__nv_bfloat162*)(sm + A_KL + so) = Kl2[g];
            *(__nv_bfloat162*)(sm + A_VH + so) = Vh2[g];
            *(__nv_bfloat162*)(sm + A_VL + so) = Vl2[g];
        }
        // St tiles [64 d][64 e], pitch 144B
        const __nv_bfloat162* Sh2 = (const __nv_bfloat162*)pkvh;
        const __nv_bfloat162* Sl2 = (const __nv_bfloat162*)pkvl;
        const size_t sbase = ((size_t)(bh*NCHUNK + c))*2048;
        #pragma unroll
        for (int t = 0; t < 8; ++t) {
            const int u = tid + t*256;                 // 0..2047
            const int dd = u >> 5, e2 = u & 31;
            const uint32_t so = dd*144 + e2*4;
            *(__nv_bfloat162*)(sm + A_STH + so) = Sh2[sbase + u];
            *(__nv_bfloat162*)(sm + A_STL + so) = Sl2[sbase + u];
        }
        if (tid < 64)
            ((float*)(sm + A_KP))[tid] = pks[(bh*NCHUNK + c)*64 + tid];
    }
    __syncthreads();

    const int qr = lane >> 2, qc = (lane & 3)*2;

    // ---- Stage 1: S = Q @ K^T (128x128x64), masked, split to Ssc hi/lo ----
    {
        float d1[4][4][4];
        #pragma unroll
        for (int mt = 0; mt < 4; ++mt)
            #pragma unroll
            for (int nt = 0; nt < 4; ++nt)
                #pragma unroll
                for (int e = 0; e < 4; ++e) d1[mt][nt][e] = 0.f;

        #pragma unroll
        for (int ks = 0; ks < 4; ++ks) {
            uint32_t ah[4][4], al[4][4];
            #pragma unroll
            for (int mt = 0; mt < 4; ++mt) {
                const uint32_t r = warp_m*64 + mt*16 + (lane & 15);
                const uint32_t addr = smb + A_QH + r*144 + ks*32 + (lane >> 4)*16;
                LDSM4(ah[mt], addr);
                LDSM4(al[mt], addr + (A_QL - A_QH));
            }
            uint32_t bh1[4][2], bl1[4][2];
            #pragma unroll
            for (int p = 0; p < 2; ++p) {
                const uint32_t r = warp_n*32 + p*16 + (lane & 7) + ((lane & 16) >> 1);
                const uint32_t addr = smb + A_KH + r*144 + ks*32 + (lane & 8)*2;
                uint32_t t[4];
                LDSM4(t, addr);
                bh1[2*p][0]=t[0]; bh1[2*p][1]=t[1]; bh1[2*p+1][0]=t[2]; bh1[2*p+1][1]=t[3];
                LDSM4(t, addr + (A_KL - A_KH));
                bl1[2*p][0]=t[0]; bl1[2*p][1]=t[1]; bl1[2*p+1][0]=t[2]; bl1[2*p+1][1]=t[3];
            }
            #pragma unroll
            for (int mt = 0; mt < 4; ++mt)
                #pragma unroll
                for (int nt = 0; nt < 4; ++nt) {
                    MMA_BF16(d1[mt][nt], ah[mt], bh1[nt]);
                    MMA_BF16(d1[mt][nt], ah[mt], bl1[nt]);
                    MMA_BF16(d1[mt][nt], al[mt], bh1[nt]);
                }
        }
        // mask (keep j<=i), split, store to Ssc (pitch 272B)
        #pragma unroll
        for (int mt = 0; mt < 4; ++mt) {
            const int i0 = warp_m*64 + mt*16 + qr, i1 = i0 + 8;
            #pragma unroll
            for (int nt = 0; nt < 4; ++nt) {
                const int j = warp_n*32 + nt*8 + qc;
                float v0 = (j   <= i0) ? d1[mt][nt][0] : 0.f;
                float v1 = (j+1 <= i0) ? d1[mt][nt][1] : 0.f;
                float v2 = (j   <= i1) ? d1[mt][nt][2] : 0.f;
                float v3 = (j+1 <= i1) ? d1[mt][nt][3] : 0.f;
                __nv_bfloat16 h0,h1,h2,h3,l0,l1,l2,l3;
                split_bf16(v0,h0,l0); split_bf16(v1,h1,l1);
                split_bf16(v2,h2,l2); split_bf16(v3,h3,l3);
                __nv_bfloat162 p0; p0.x=h0; p0.y=h1;
                __nv_bfloat162 p1; p1.x=h2; p1.y=h3;
                __nv_bfloat162 q0; q0.x=l0; q0.y=l1;
                __nv_bfloat162 q1; q1.x=l2; q1.y=l3;
                *(__nv_bfloat162*)(sm + A_SCH + i0*272 + j*2) = p0;
                *(__nv_bfloat162*)(sm + A_SCH + i1*272 + j*2) = p1;
                *(__nv_bfloat162*)(sm + A_SCL + i0*272 + j*2) = q0;
                *(__nv_bfloat162*)(sm + A_SCL + i1*272 + j*2) = q1;
            }
        }
    }
    __syncthreads();

    // ---- Stage 2: denominators ----
    {
        const int i = tid >> 1, half = tid & 1;
        float s = 0.f;
        const char* rh = sm + A_SCH + i*272 + half*128;
        const char* rl = sm + A_SCL + i*272 + half*128;
        #pragma unroll
        for (int j2 = 0; j2 < 32; ++j2) {
            __nv_bfloat162 ph = *(const __nv_bfloat162*)(rh + j2*4);
            __nv_bfloat162 pl = *(const __nv_bfloat162*)(rl + j2*4);
            s += (__bfloat162float(ph.x) + __bfloat162float(pl.x))
               + (__bfloat162float(ph.y) + __bfloat162float(pl.y));
        }
        const float* kp = (const float*)(sm + A_KP);
        const char* qh = sm + A_QH + i*144 + half*64;
        const char* ql = sm + A_QL + i*144 + half*64;
        #pragma unroll
        for (int k2 = 0; k2 < 16; ++k2) {
            __nv_bfloat162 ph = *(const __nv_bfloat162*)(qh + k2*4);
            __nv_bfloat162 pl = *(const __nv_bfloat162*)(ql + k2*4);
            const int k = half*32 + k2*2;
            s = fmaf(__bfloat162float(ph.x) + __bfloat162float(pl.x), kp[k],   s);
            s = fmaf(__bfloat162float(ph.y) + __bfloat162float(pl.y), kp[k+1], s);
        }
        s += __shfl_xor_sync(0xffffffffu, s, 1);
        if (half == 0)
            ((float*)(sm + A_DLOC))[i] = 1.f / (s*ATT_SCALE + ATT_EPS);
    }
    __syncthreads();

    // ---- Stage 3: O = Ssc @ V + Q @ St (128x64x(128+64)) ----
    {
        float d3[4][2][4];
        #pragma unroll
        for (int mt = 0; mt < 4; ++mt)
            #pragma unroll
            for (int nt = 0; nt < 2; ++nt)
                #pragma unroll
                for (int e = 0; e < 4; ++e) d3[mt][nt][e] = 0.f;

        // part A: Ssc @ V (k = j, 8 ksteps of 16); V row-major [j][e] -> trans
        #pragma unroll
        for (int ks = 0; ks < 8; ++ks) {
            uint32_t ah[4][4], al[4][4];
            #pragma unroll
            for (int mt = 0; mt < 4; ++mt) {
                const uint32_t r = warp_m*64 + mt*16 + (lane & 15);
                const uint32_t addr = smb + A_SCH + r*272 + ks*32 + (lane >> 4)*16;
                LDSM4(ah[mt], addr);
                LDSM4(al[mt], addr + (A_SCL - A_SCH));
            }
            uint32_t bh3[2][2], bl3[2][2];
            {
                const uint32_t addr = smb + A_VH + (ks*16 + (lane & 15))*144
                                    + (warp_n*16 + (lane >> 4)*8)*2;
                uint32_t t[4];
                LDSM4T(t, addr);
                bh3[0][0]=t[0]; bh3[0][1]=t[1]; bh3[1][0]=t[2]; bh3[1][1]=t[3];
                LDSM4T(t, addr + (A_VL - A_VH));
                bl3[0][0]=t[0]; bl3[0][1]=t[1]; bl3[1][0]=t[2]; bl3[1][1]=t[3];
            }
            #pragma unroll
            for (int mt = 0; mt < 4; ++mt)
                #pragma unroll
                for (int nt = 0; nt < 2; ++nt) {
                    MMA_BF16(d3[mt][nt], ah[mt], bh3[nt]);
                    MMA_BF16(d3[mt][nt], ah[mt], bl3[nt]);
                    MMA_BF16(d3[mt][nt], al[mt], bh3[nt]);
                }
        }
        // part B: Q @ St (k = d, 4 ksteps); St row-major [d][e] -> trans
        #pragma unroll
        for (int ks = 0; ks < 4; ++ks) {
            uint32_t ah[4][4], al[4][4];
            #pragma unroll
            for (int mt = 0; mt < 4; ++mt) {
                const uint32_t r = warp_m*64 + mt*16 + (lane & 15);
                const uint32_t addr = smb + A_QH + r*144 + ks*32 + (lane >> 4)*16;
                LDSM4(ah[mt], addr);
                LDSM4(al[mt], addr + (A_QL - A_QH));
            }
            uint32_t bh3[2][2], bl3[2][2];
            {
                const uint32_t addr = smb + A_STH + (ks*16 + (lane & 15))*144
                                    + (warp_n*16 + (lane >> 4)*8)*2;
                uint32_t t[4];
                LDSM4T(t, addr);
                bh3[0][0]=t[0]; bh3[0][1]=t[1]; bh3[1][0]=t[2]; bh3[1][1]=t[3];
                LDSM4T(t, addr + (A_STL - A_STH));
                bl3[0][0]=t[0]; bl3[0][1]=t[1]; bl3[1][0]=t[2]; bl3[1][1]=t[3];
            }
            #pragma unroll
            for (int mt = 0; mt < 4; ++mt)
                #pragma unroll
                for (int nt = 0; nt < 2; ++nt) {
                    MMA_BF16(d3[mt][nt], ah[mt], bh3[nt]);
                    MMA_BF16(d3[mt][nt], ah[mt], bl3[nt]);
                    MMA_BF16(d3[mt][nt], al[mt], bh3[nt]);
                }
        }

        // scale + split + write AV
        const float* dloc = (const float*)(sm + A_DLOC);
        __nv_bfloat162* AVh2 = (__nv_bfloat162*)AVh;
        __nv_bfloat162* AVl2 = (__nv_bfloat162*)AVl;
        #pragma unroll
        for (int mt = 0; mt < 4; ++mt) {
            const int i0 = warp_m*64 + mt*16 + qr, i1 = i0 + 8;
            const float sc0 = ATT_SCALE * dloc[i0];
            const float sc1 = ATT_SCALE * dloc[i1];
            const size_t g0 = (size_t)((c*CHUNK + i0)*BATCH + b)*256 + hh*32;
            const size_t g1 = (size_t)((c*CHUNK + i1)*BATCH + b)*256 + hh*32;
            #pragma unroll
            for (int nt = 0; nt < 2; ++nt) {
                const int n = warp_n*16 + nt*8 + qc;
                float v0 = d3[mt][nt][0]*sc0, v1 = d3[mt][nt][1]*sc0;
                float v2 = d3[mt][nt][2]*sc1, v3 = d3[mt][nt][3]*sc1;
                __nv_bfloat16 h0,h1,h2,h3,l0,l1,l2,l3;
                split_bf16(v0,h0,l0); split_bf16(v1,h1,l1);
                split_bf16(v2,h2,l2); split_bf16(v3,h3,l3);
                __nv_bfloat162 p0; p0.x=h0; p0.y=h1;
                __nv_bfloat162 p1; p1.x=h2; p1.y=h3;
                __nv_bfloat162 q0; q0.x=l0; q0.y=l1;
                __nv_bfloat162 q1; q1.x=l2; q1.y=l3;
                AVh2[g0 + (n >> 1)] = p0;
                AVh2[g1 + (n >> 1)] = p1;
                AVl2[g0 + (n >> 1)] = q0;
                AVl2[g1 + (n >> 1)] = q1;
            }
        }
    }
}

// ---------------------------------------------------------------------------
// LayerNorm(h + attn_out). One block per row (512 cols), 128 threads.
// ---------------------------------------------------------------------------
__global__ __launch_bounds__(128) void ln_kernel(
    const float* __restrict__ h, const float* __restrict__ ao,
    const float* __restrict__ gamma, const float* __restrict__ beta,
    float* __restrict__ out)
{
    const int row = blockIdx.x;
    const int tid = threadIdx.x;
    __shared__ float red[4];

    const float* hp = h  + (size_t)row*512;
    const float* ap = ao + (size_t)row*512;
    float x[4];
    #pragma unroll
    for (int r = 0; r < 4; ++r) x[r] = hp[tid + r*128] + ap[tid + r*128];

    float s = (x[0] + x[1]) + (x[2] + x[3]);
    #pragma unroll
    for (int o = 16; o > 0; o >>= 1) s += __shfl_xor_sync(0xffffffffu, s, o);
    if ((tid & 31) == 0) red[tid >> 5] = s;
    __syncthreads();
    const float mu = (red[0] + red[1] + red[2] + red[3]) * (1.f/512.f);
    __syncthreads();

    float v = 0.f;
    #pragma unroll
    for (int r = 0; r < 4; ++r) { const float d = x[r] - mu; v = fmaf(d, d, v); }
    #pragma unroll
    for (int o = 16; o > 0; o >>= 1) v += __shfl_xor_sync(0xffffffffu, v, o);
    if ((tid & 31) == 0) red[tid >> 5] = v;
    __syncthreads();
    const float var  = (red[0] + red[1] + red[2] + red[3]) * (1.f/512.f);
    const float rstd = rsqrtf(var + LN_EPS);

    #pragma unroll
    for (int r = 0; r < 4; ++r) {
        const int col = tid + r*128;
        out[(size_t)row*512 + col] = (x[r] - mu)*rstd*gamma[col] + beta[col];
    }
}

// ---------------------------------------------------------------------------
extern "C" void kernel_launch(void* const* d_in, const int* in_sizes, int n_in,
                              void* d_out, int out_size)
{
    (void)in_sizes; (void)n_in; (void)out_size;
    const float* h     = (const float*)d_in[0];
    const float* Wq    = (const float*)d_in[1];
    const float* Wkv   = (const float*)d_in[2];
    const float* Wo    = (const float*)d_in[3];
    const float* gamma = (const float*)d_in[4];
    const float* beta  = (const float*)d_in[5];
    float* out = (float*)d_out;

    __nv_bfloat16 *hh, *hl, *Wqh, *Wql, *Wkvh, *Wkvl, *Woh, *Wol;
    __nv_bfloat16 *Qh, *Ql, *Kh, *Kl, *Vh, *Vl, *pkvh, *pkvl, *AVh, *AVl;
    float *ckv, *cks, *pks, *AO;
    cudaGetSymbolAddress((void**)&hh,   g_hh);
    cudaGetSymbolAddress((void**)&hl,   g_hl);
    cudaGetSymbolAddress((void**)&Wqh,  g_Wqh);
    cudaGetSymbolAddress((void**)&Wql,  g_Wql);
    cudaGetSymbolAddress((void**)&Wkvh, g_Wkvh);
    cudaGetSymbolAddress((void**)&Wkvl, g_Wkvl);
    cudaGetSymbolAddress((void**)&Woh,  g_Woh);
    cudaGetSymbolAddress((void**)&Wol,  g_Wol);
    cudaGetSymbolAddress((void**)&Qh,   g_Qh);
    cudaGetSymbolAddress((void**)&Ql,   g_Ql);
    cudaGetSymbolAddress((void**)&Kh,   g_Kh);
    cudaGetSymbolAddress((void**)&Kl,   g_Kl);
    cudaGetSymbolAddress((void**)&Vh,   g_Vh);
    cudaGetSymbolAddress((void**)&Vl,   g_Vl);
    cudaGetSymbolAddress((void**)&ckv,  g_ckv);
    cudaGetSymbolAddress((void**)&cks,  g_cks);
    cudaGetSymbolAddress((void**)&pkvh, g_pkvh);
    cudaGetSymbolAddress((void**)&pkvl, g_pkvl);
    cudaGetSymbolAddress((void**)&pks,  g_pks);
    cudaGetSymbolAddress((void**)&AVh,  g_AVh);
    cudaGetSymbolAddress((void**)&AVl,  g_AVl);
    cudaGetSymbolAddress((void**)&AO,   g_AO);

    constexpr int GEMM_SMEM = 2 * (2*128*80 + 2*32*272);   // 75776 bytes

    cudaFuncSetAttribute(gemm_mma<0>, cudaFuncAttributeMaxDynamicSharedMemorySize, GEMM_SMEM);
    cudaFuncSetAttribute(gemm_mma<1>, cudaFuncAttributeMaxDynamicSharedMemorySize, GEMM_SMEM);
    cudaFuncSetAttribute(gemm_mma<2>, cudaFuncAttributeMaxDynamicSharedMemorySize, GEMM_SMEM);
    cudaFuncSetAttribute(attn_kernel, cudaFuncAttributeMaxDynamicSharedMemorySize, ATTN_SMEM_BYTES);

    // 0. elementwise splits (no transpose needed anymore)
    split_kernel<<<(NROWS*DMODEL/4 + 255)/256, 256>>>(h,   hh,   hl,   NROWS*DMODEL/4);
    split_kernel<<<(512*512/4 + 255)/256, 256>>>(Wq,  Wqh,  Wql,  512*512/4);
    split_kernel<<<(512*1024/4 + 255)/256, 256>>>(Wkv, Wkvh, Wkvl, 512*1024/4);
    split_kernel<<<(512*512/4 + 255)/256, 256>>>(Wo,  Woh,  Wol,  512*512/4);

    // 1. Q = elu1(h @ Wq) -> bf16 hi/lo
    gemm_mma<1><<<dim3(4, 32), 256, GEMM_SMEM>>>(hh, hl, Wqh, Wql,
        nullptr, Qh, Ql, nullptr, nullptr, 512, 512);
    // 2. KV = h @ Wkv -> K (elu1) hi/lo, V hi/lo
    gemm_mma<2><<<dim3(8, 32), 256, GEMM_SMEM>>>(hh, hl, Wkvh, Wkvl,
        nullptr, Kh, Kl, Vh, Vl, 1024, 512);

    // 3. chunked linear attention
    chunk_kv_kernel<<<dim3(NCHUNK, NBH), 256>>>(Kh, Kl, Vh, Vl, ckv, cks);
    prefix_kernel<<<dim3(NBH, 16), 256>>>(ckv, cks, pkvh, pkvl, pks);
    attn_kernel<<<dim3(NCHUNK, NBH), 256, ATTN_SMEM_BYTES>>>(
        Qh, Ql, Kh, Kl, Vh, Vl, pkvh, pkvl, pks, AVh, AVl);

    // 4. attn_out = attn_vec @ Wo (fp32 out)
    gemm_mma<0><<<dim3(4, 32), 256, GEMM_SMEM>>>(AVh, AVl, Woh, Wol,
        AO, nullptr, nullptr, nullptr, nullptr, 512, 512);

    // 5. out = LayerNorm(h + attn_out)
    ln_kernel<<<NROWS, 128>>>(h, AO, gamma, beta, out);
}

// round 5
// speedup vs baseline: 2.9453x; 1.4966x over previous
#include <cuda_runtime.h>
#include <cuda_fp16.h>
#include <cstdint>
#include <math.h>

// Problem constants
#define S_LEN   2048
#define BATCH   2
#define DMODEL  512
#define NHEAD   8
#define DHEAD   64
#define NROWS   (S_LEN*BATCH)        // 4096
#define CHUNK   128
#define NCHUNK  (S_LEN/CHUNK)        // 16
#define NBH     (BATCH*NHEAD)        // 16
#define ATT_SCALE 0.125f
#define ATT_EPS   1e-5f
#define LN_EPS    1e-5f

// ---------------------------------------------------------------------------
// PTX helpers — arch-agnostic (plain sm_103 target: no tcgen05)
// ---------------------------------------------------------------------------
__device__ __forceinline__ uint32_t smem_u32(const void* p) {
    uint32_t a;
    asm("{ .reg .u64 t; cvta.to.shared.u64 t, %1; cvt.u32.u64 %0, t; }"
        : "=r"(a) : "l"(p));
    return a;
}

#define LDSM4(r, addr) \
    asm volatile("ldmatrix.sync.aligned.m8n8.x4.shared.b16 {%0,%1,%2,%3}, [%4];" \
        : "=r"((r)[0]), "=r"((r)[1]), "=r"((r)[2]), "=r"((r)[3]) : "r"(addr))

#define LDSM4T(r, addr) \
    asm volatile("ldmatrix.sync.aligned.m8n8.x4.trans.shared.b16 {%0,%1,%2,%3}, [%4];" \
        : "=r"((r)[0]), "=r"((r)[1]), "=r"((r)[2]), "=r"((r)[3]) : "r"(addr))

#define MMA_F16(d, a, b) \
    asm volatile("mma.sync.aligned.m16n8k16.row.col.f32.f16.f16.f32 " \
        "{%0,%1,%2,%3}, {%4,%5,%6,%7}, {%8,%9}, {%0,%1,%2,%3};" \
        : "+f"((d)[0]), "+f"((d)[1]), "+f"((d)[2]), "+f"((d)[3]) \
        : "r"((a)[0]), "r"((a)[1]), "r"((a)[2]), "r"((a)[3]), \
          "r"((b)[0]), "r"((b)[1]))

#define CP_ASYNC16(sdst, gsrc) \
    asm volatile("cp.async.cg.shared.global [%0], [%1], 16;" \
        :: "r"(sdst), "l"(gsrc) : "memory")
#define CP_COMMIT() asm volatile("cp.async.commit_group;" ::: "memory")
#define CP_WAIT2()  asm volatile("cp.async.wait_group 2;" ::: "memory")

// ---------------------------------------------------------------------------
// Scratch (static device globals — no allocation allowed)
// ---------------------------------------------------------------------------
__device__ __half g_h16 [NROWS*DMODEL];
__device__ __half g_Wq16 [512*512];
__device__ __half g_Wkv16[512*1024];
__device__ __half g_Wo16 [512*512];

__device__ __half g_Q[NROWS*DMODEL];
__device__ __half g_K[NROWS*DMODEL];
__device__ __half g_V[NROWS*DMODEL];

__device__ float g_ckv[NBH*NCHUNK*DHEAD*DHEAD];
__device__ float g_cks[NBH*NCHUNK*DHEAD];
__device__ __half g_pkv[NBH*NCHUNK*DHEAD*DHEAD];
__device__ float g_pks[NBH*NCHUNK*DHEAD];

__device__ __half g_AV[NROWS*DMODEL];
__device__ float  g_AO[NROWS*DMODEL];

__device__ __forceinline__ float elu1(float x) {
    return x > 0.f ? x + 1.f : expf(x);
}

// ---------------------------------------------------------------------------
// Fused split: convert all four fp32 tensors to fp16 in ONE launch.
// grid = 3072 blocks x 256 threads, each thread converts 4 floats.
// ---------------------------------------------------------------------------
__global__ __launch_bounds__(256) void convert_all_kernel(
    const float* __restrict__ h,  const float* __restrict__ Wq,
    const float* __restrict__ Wkv, const float* __restrict__ Wo,
    __half* __restrict__ h16, __half* __restrict__ wq16,
    __half* __restrict__ wkv16, __half* __restrict__ wo16)
{
    const int bid = blockIdx.x;
    const float* src; __half* dst; int i;
    if (bid < 2048)      { src = h;   dst = h16;   i = bid*256 + threadIdx.x; }
    else if (bid < 2304) { src = Wq;  dst = wq16;  i = (bid-2048)*256 + threadIdx.x; }
    else if (bid < 2816) { src = Wkv; dst = wkv16; i = (bid-2304)*256 + threadIdx.x; }
    else                 { src = Wo;  dst = wo16;  i = (bid-2816)*256 + threadIdx.x; }
    float4 v = ((const float4*)src)[i];
    __half2 p0; p0.x = __float2half_rn(v.x); p0.y = __float2half_rn(v.y);
    __half2 p1; p1.x = __float2half_rn(v.z); p1.y = __float2half_rn(v.w);
    ((__half2*)dst)[2*i]   = p0;
    ((__half2*)dst)[2*i+1] = p1;
}

// ---------------------------------------------------------------------------
// Single-term fp16 mma.sync GEMM: C[M,N] = A[M,K] @ W[K,N]  (W row-major)
// 128x128 CTA tile, 8 warps (2x4), warp tile 64x32, K-chunks of 32,
// 3-stage cp.async pipeline, fp32 accumulate.
// MODE 0: fp32 out to C
// MODE 1: elu+1 -> D1 fp16                              [Q]
// MODE 2: n0<512: elu+1 -> D1 (K); else -> D2 (V, col-512)
// ---------------------------------------------------------------------------
template<int MODE>
__global__ __launch_bounds__(256, 1) void gemm_mma(
    const __half* __restrict__ A, const __half* __restrict__ B,
    float* __restrict__ C, __half* __restrict__ D1, __half* __restrict__ D2,
    int N, int K)
{
    extern __shared__ char smem[];
    constexpr uint32_t TILEA = 128*80;     // 128 m x 32 k fp16, 80B pitch
    constexpr uint32_t TILEB = 32*272;     // 32 k x 128 n fp16, 272B pitch
    constexpr uint32_t BUFB  = TILEA + TILEB;   // 18944

    const int tid = threadIdx.x;
    const int wid = tid >> 5, lane = tid & 31;
    const int m0 = blockIdx.y*128, n0 = blockIdx.x*128;
    const int warp_m = wid >> 2, warp_n = wid & 3;
    const uint32_t smb = smem_u32(smem);

    auto issue_chunk = [&](int kt, int buf) {
        const uint32_t sbase = smb + (uint32_t)buf*BUFB;
        #pragma unroll
        for (int half_ = 0; half_ < 2; ++half_) {
            const int idx = tid + half_*256;           // 0..511
            const int ar = idx >> 2, ac = idx & 3;
            const uint32_t asoff = (uint32_t)(ar*80 + ac*16);
            const size_t ga = (size_t)(m0 + ar)*K + (size_t)kt*32 + ac*8;
            CP_ASYNC16(sbase + asoff, A + ga);
            const int br = idx >> 4, bc = idx & 15;
            const uint32_t bsoff = (uint32_t)(br*272 + bc*16);
            const size_t gb = (size_t)(kt*32 + br)*N + n0 + bc*8;
            CP_ASYNC16(sbase + TILEA + bsoff, B + gb);
        }
        CP_COMMIT();
    };

    float d[4][4][4];
    #pragma unroll
    for (int mt = 0; mt < 4; ++mt)
        #pragma unroll
        for (int nt = 0; nt < 4; ++nt)
            #pragma unroll
            for (int e = 0; e < 4; ++e) d[mt][nt][e] = 0.f;

    const int NT = K >> 5;                 // 16
    issue_chunk(0, 0);
    issue_chunk(1, 1);
    issue_chunk(2, 2);

    for (int kt = 0; kt < NT; ++kt) {
        CP_WAIT2();
        __syncthreads();
        const int buf = kt % 3;
        const uint32_t sA = smb + (uint32_t)buf*BUFB;
        const uint32_t sB = sA + TILEA;

        #pragma unroll
        for (int k16 = 0; k16 < 2; ++k16) {
            uint32_t a[4][4];
            #pragma unroll
            for (int mt = 0; mt < 4; ++mt) {
                const uint32_t r = warp_m*64 + mt*16 + (lane & 15);
                LDSM4(a[mt], sA + r*80 + k16*32 + (lane >> 4)*16);
            }
            uint32_t bfr[4][2];
            #pragma unroll
            for (int p = 0; p < 2; ++p) {
                const uint32_t addr = sB + (k16*16 + (lane & 15))*272
                                    + (warp_n*32 + p*16 + (lane >> 4)*8)*2;
                uint32_t t[4];
                LDSM4T(t, addr);
                bfr[2*p][0] = t[0]; bfr[2*p][1] = t[1];
                bfr[2*p+1][0] = t[2]; bfr[2*p+1][1] = t[3];
            }
            #pragma unroll
            for (int mt = 0; mt < 4; ++mt)
                #pragma unroll
                for (int nt = 0; nt < 4; ++nt)
                    MMA_F16(d[mt][nt], a[mt], bfr[nt]);
        }
        __syncthreads();
        if (kt + 3 < NT) issue_chunk(kt + 3, buf);
    }

    // Epilogue
    const int mb = m0 + warp_m*64;
    const int qr = lane >> 2, qc = (lane & 3)*2;
    #pragma unroll
    for (int mt = 0; mt < 4; ++mt) {
        const int r0 = mb + mt*16 + qr, r1 = r0 + 8;
        #pragma unroll
        for (int nt = 0; nt < 4; ++nt) {
            const int n = n0 + warp_n*32 + nt*8 + qc;
            float v0 = d[mt][nt][0], v1 = d[mt][nt][1];
            float v2 = d[mt][nt][2], v3 = d[mt][nt][3];
            if (MODE == 0) {
                float2 p0; p0.x = v0; p0.y = v1;
                float2 p1; p1.x = v2; p1.y = v3;
                *(float2*)&C[(size_t)r0*N + n] = p0;
                *(float2*)&C[(size_t)r1*N + n] = p1;
            } else {
                __half* dst; int col; bool do_elu;
                if (MODE == 1) { dst = D1; col = n; do_elu = true; }
                else if (n0 < 512) { dst = D1; col = n; do_elu = true; }
                else { dst = D2; col = n - 512; do_elu = false; }
                if (do_elu) { v0 = elu1(v0); v1 = elu1(v1); v2 = elu1(v2); v3 = elu1(v3); }
                __half2 p0; p0.x = __float2half_rn(v0); p0.y = __float2half_rn(v1);
                __half2 p1; p1.x = __float2half_rn(v2); p1.y = __float2half_rn(v3);
                *(__half2*)&dst[(size_t)r0*512 + col] = p0;
                *(__half2*)&dst[(size_t)r1*512 + col] = p1;
            }
        }
    }
}

// ---------------------------------------------------------------------------
// Per-chunk KV outer-product sums + K sums. grid (NCHUNK, NBH), 256 threads.
// ---------------------------------------------------------------------------
__global__ __launch_bounds__(256) void chunk_kv_kernel(
    const __half* __restrict__ K16, const __half* __restrict__ V16,
    float* __restrict__ ckv, float* __restrict__ cks)
{
    const int c  = blockIdx.x, bh = blockIdx.y;
    const int b  = bh >> 3, hh = bh & 7;
    const int tid = threadIdx.x;

    __shared__ float sk[4][64], sv[4][64];

    const int d  = tid >> 2;
    const int e0 = (tid & 3) << 4;
    const int jj = tid >> 6, dd = tid & 63;

    float acc[16];
    #pragma unroll
    for (int r = 0; r < 16; ++r) acc[r] = 0.f;
    float ksum = 0.f;

    for (int j0 = 0; j0 < CHUNK; j0 += 4) {
        const int s = c*CHUNK + j0 + jj;
        const size_t base = ((size_t)(s*BATCH + b))*512 + hh*64 + dd;
        const float kk_in = __half2float(K16[base]);
        const float vv_in = __half2float(V16[base]);
        __syncthreads();
        sk[jj][dd] = kk_in;
        sv[jj][dd] = vv_in;
        __syncthreads();
        #pragma unroll
        for (int q = 0; q < 4; ++q) {
            const float kk = sk[q][d];
            #pragma unroll
            for (int r = 0; r < 16; ++r)
                acc[r] = fmaf(kk, sv[q][e0 + r], acc[r]);
        }
        if (tid < 64)
            ksum += sk[0][tid] + sk[1][tid] + sk[2][tid] + sk[3][tid];
    }

    float* outp = ckv + (((size_t)bh*NCHUNK + c) << 12) + d*64 + e0;
    #pragma unroll
    for (int r = 0; r < 16; ++r) outp[r] = acc[r];
    if (tid < 64) cks[(bh*NCHUNK + c)*64 + tid] = ksum;
}

// ---------------------------------------------------------------------------
// Exclusive prefix over chunks — St out as fp16. grid (NBH, 16), 256 threads.
// ---------------------------------------------------------------------------
__global__ __launch_bounds__(256) void prefix_kernel(
    const float* __restrict__ ckv, const float* __restrict__ cks,
    __half* __restrict__ pkv, float* __restrict__ pks)
{
    const int bh  = blockIdx.x;
    const int idx = blockIdx.y*256 + threadIdx.x;      // 0..4095
    const size_t base = ((size_t)bh*NCHUNK) << 12;

    float v[NCHUNK];
    #pragma unroll
    for (int c = 0; c < NCHUNK; ++c) v[c] = ckv[base + ((size_t)c << 12) + idx];
    float acc = 0.f;
    #pragma unroll
    for (int c = 0; c < NCHUNK; ++c) {
        pkv[base + ((size_t)c << 12) + idx] = __float2half_rn(acc);
        acc += v[c];
    }
    if (blockIdx.y == 0 && threadIdx.x < 64) {
        const int t = threadIdx.x;
        float s[NCHUNK];
        #pragma unroll
        for (int c = 0; c < NCHUNK; ++c) s[c] = cks[(bh*NCHUNK + c)*64 + t];
        float a = 0.f;
        #pragma unroll
        for (int c = 0; c < NCHUNK; ++c) {
            pks[(bh*NCHUNK + c)*64 + t] = a;
            a += s[c];
        }
    }
}

// ---------------------------------------------------------------------------
// Tensor-core chunked linear attention, fp16 single-term.
// grid (NCHUNK, NBH), 256 threads, ~100KB dynamic smem (2 CTA/SM => 1 wave).
// ---------------------------------------------------------------------------
#define A_Q    0u
#define A_K    18432u
#define A_V    36864u
#define A_ST   55296u
#define A_SC   64512u
#define A_KP   99328u
#define A_DLOC 99584u
#define ATTN_SMEM_BYTES 100096

__global__ __launch_bounds__(256, 2) void attn_kernel(
    const __half* __restrict__ Q16, const __half* __restrict__ K16,
    const __half* __restrict__ V16, const __half* __restrict__ pkv,
    const float* __restrict__ pks, __half* __restrict__ AV)
{
    extern __shared__ char sm[];
    const uint32_t smb = smem_u32(sm);

    const int c  = blockIdx.x, bh = blockIdx.y;
    const int b  = bh >> 3, hh = bh & 7;
    const int tid = threadIdx.x;
    const int wid = tid >> 5, lane = tid & 31;
    const int warp_m = wid >> 2, warp_n = wid & 3;

    // ---- loads: Q/K/V tiles [128 rows][64 k] fp16, pitch 144B ----
    {
        const __half2* Q2 = (const __half2*)Q16;
        const __half2* K2 = (const __half2*)K16;
        const __half2* V2 = (const __half2*)V16;
        #pragma unroll
        for (int t = 0; t < 16; ++t) {
            const int u = tid + t*256;                 // 0..4095
            const int row = u >> 5, c2 = u & 31;
            const size_t g = (size_t)((c*CHUNK + row)*BATCH + b)*256 + hh*32 + c2;
            const uint32_t so = row*144 + c2*4;
            *(__half2*)(sm + A_Q + so) = Q2[g];
            *(__half2*)(sm + A_K + so) = K2[g];
            *(__half2*)(sm + A_V + so) = V2[g];
        }
        const __half2* S2 = (const __half2*)pkv;
        const size_t sbase = ((size_t)(bh*NCHUNK + c))*2048;
        #pragma unroll
        for (int t = 0; t < 8; ++t) {
            const int u = tid + t*256;                 // 0..2047
            const int dd = u >> 5, e2 = u & 31;
            *(__half2*)(sm + A_ST + dd*144 + e2*4) = S2[sbase + u];
        }
        if (tid < 64)
            ((float*)(sm + A_KP))[tid] = pks[(bh*NCHUNK + c)*64 + tid];
    }
    __syncthreads();

    const int qr = lane >> 2, qc = (lane & 3)*2;

    // ---- Stage 1: S = Q @ K^T (128x128x64), masked -> Ssc fp16 ----
    {
        float d1[4][4][4];
        #pragma unroll
        for (int mt = 0; mt < 4; ++mt)
            #pragma unroll
            for (int nt = 0; nt < 4; ++nt)
                #pragma unroll
                for (int e = 0; e < 4; ++e) d1[mt][nt][e] = 0.f;

        #pragma unroll
        for (int ks = 0; ks < 4; ++ks) {
            uint32_t a[4][4];
            #pragma unroll
            for (int mt = 0; mt < 4; ++mt) {
                const uint32_t r = warp_m*64 + mt*16 + (lane & 15);
                LDSM4(a[mt], smb + A_Q + r*144 + ks*32 + (lane >> 4)*16);
            }
            uint32_t bf[4][2];
            #pragma unroll
            for (int p = 0; p < 2; ++p) {
                const uint32_t r = warp_n*32 + p*16 + (lane & 7) + ((lane & 16) >> 1);
                uint32_t t[4];
                LDSM4(t, smb + A_K + r*144 + ks*32 + (lane & 8)*2);
                bf[2*p][0]=t[0]; bf[2*p][1]=t[1]; bf[2*p+1][0]=t[2]; bf[2*p+1][1]=t[3];
            }
            #pragma unroll
            for (int mt = 0; mt < 4; ++mt)
                #pragma unroll
                for (int nt = 0; nt < 4; ++nt)
                    MMA_F16(d1[mt][nt], a[mt], bf[nt]);
        }
        #pragma unroll
        for (int mt = 0; mt < 4; ++mt) {
            const int i0 = warp_m*64 + mt*16 + qr, i1 = i0 + 8;
            #pragma unroll
            for (int nt = 0; nt < 4; ++nt) {
                const int j = warp_n*32 + nt*8 + qc;
                float v0 = (j   <= i0) ? d1[mt][nt][0] : 0.f;
                float v1 = (j+1 <= i0) ? d1[mt][nt][1] : 0.f;
                float v2 = (j   <= i1) ? d1[mt][nt][2] : 0.f;
                float v3 = (j+1 <= i1) ? d1[mt][nt][3] : 0.f;
                __half2 p0; p0.x = __float2half_rn(v0); p0.y = __float2half_rn(v1);
                __half2 p1; p1.x = __float2half_rn(v2); p1.y = __float2half_rn(v3);
                *(__half2*)(sm + A_SC + i0*272 + j*2) = p0;
                *(__half2*)(sm + A_SC + i1*272 + j*2) = p1;
            }
        }
    }
    __syncthreads();

    // ---- Stage 2: denominators ----
    {
        const int i = tid >> 1, half_ = tid & 1;
        float s = 0.f;
        const char* rh = sm + A_SC + i*272 + half_*128;
        #pragma unroll
        for (int j2 = 0; j2 < 32; ++j2) {
            __half2 ph = *(const __half2*)(rh + j2*4);
            s += __half2float(ph.x) + __half2float(ph.y);
        }
        const float* kp = (const float*)(sm + A_KP);
        const char* qh = sm + A_Q + i*144 + half_*64;
        #pragma unroll
        for (int k2 = 0; k2 < 16; ++k2) {
            __half2 ph = *(const __half2*)(qh + k2*4);
            const int k = half_*32 + k2*2;
            s = fmaf(__half2float(ph.x), kp[k],   s);
            s = fmaf(__half2float(ph.y), kp[k+1], s);
        }
        s += __shfl_xor_sync(0xffffffffu, s, 1);
        if (half_ == 0)
            ((float*)(sm + A_DLOC))[i] = 1.f / (s*ATT_SCALE + ATT_EPS);
    }
    __syncthreads();

    // ---- Stage 3: O = Ssc @ V + Q @ St ----
    {
        float d3[4][2][4];
        #pragma unroll
        for (int mt = 0; mt < 4; ++mt)
            #pragma unroll
            for (int nt = 0; nt < 2; ++nt)
                #pragma unroll
                for (int e = 0; e < 4; ++e) d3[mt][nt][e] = 0.f;

        // part A: Ssc @ V (8 ksteps of 16); V row-major -> trans
        #pragma unroll
        for (int ks = 0; ks < 8; ++ks) {
            uint32_t a[4][4];
            #pragma unroll
            for (int mt = 0; mt < 4; ++mt) {
                const uint32_t r = warp_m*64 + mt*16 + (lane & 15);
                LDSM4(a[mt], smb + A_SC + r*272 + ks*32 + (lane >> 4)*16);
            }
            uint32_t bf[2][2];
            {
                const uint32_t addr = smb + A_V + (ks*16 + (lane & 15))*144
                                    + (warp_n*16 + (lane >> 4)*8)*2;
                uint32_t t[4];
                LDSM4T(t, addr);
                bf[0][0]=t[0]; bf[0][1]=t[1]; bf[1][0]=t[2]; bf[1][1]=t[3];
            }
            #pragma unroll
            for (int mt = 0; mt < 4; ++mt)
                #pragma unroll
                for (int nt = 0; nt < 2; ++nt)
                    MMA_F16(d3[mt][nt], a[mt], bf[nt]);
        }
        // part B: Q @ St (4 ksteps); St row-major -> trans
        #pragma unroll
        for (int ks = 0; ks < 4; ++ks) {
            uint32_t a[4][4];
            #pragma unroll
            for (int mt = 0; mt < 4; ++mt) {
                const uint32_t r = warp_m*64 + mt*16 + (lane & 15);
                LDSM4(a[mt], smb + A_Q + r*144 + ks*32 + (lane >> 4)*16);
            }
            uint32_t bf[2][2];
            {
                const uint32_t addr = smb + A_ST + (ks*16 + (lane & 15))*144
                                    + (warp_n*16 + (lane >> 4)*8)*2;
                uint32_t t[4];
                LDSM4T(t, addr);
                bf[0][0]=t[0]; bf[0][1]=t[1]; bf[1][0]=t[2]; bf[1][1]=t[3];
            }
            #pragma unroll
            for (int mt = 0; mt < 4; ++mt)
                #pragma unroll
                for (int nt = 0; nt < 2; ++nt)
                    MMA_F16(d3[mt][nt], a[mt], bf[nt]);
        }

        const float* dloc = (const float*)(sm + A_DLOC);
        __half2* AV2 = (__half2*)AV;
        #pragma unroll
        for (int mt = 0; mt < 4; ++mt) {
            const int i0 = warp_m*64 + mt*16 + qr, i1 = i0 + 8;
            const float sc0 = ATT_SCALE * dloc[i0];
            const float sc1 = ATT_SCALE * dloc[i1];
            const size_t g0 = (size_t)((c*CHUNK + i0)*BATCH + b)*256 + hh*32;
            const size_t g1 = (size_t)((c*CHUNK + i1)*BATCH + b)*256 + hh*32;
            #pragma unroll
            for (int nt = 0; nt < 2; ++nt) {
                const int n = warp_n*16 + nt*8 + qc;
                __half2 p0, p1;
                p0.x = __float2half_rn(d3[mt][nt][0]*sc0);
                p0.y = __float2half_rn(d3[mt][nt][1]*sc0);
                p1.x = __float2half_rn(d3[mt][nt][2]*sc1);
                p1.y = __float2half_rn(d3[mt][nt][3]*sc1);
                AV2[g0 + (n >> 1)] = p0;
                AV2[g1 + (n >> 1)] = p1;
            }
        }
    }
}

// ---------------------------------------------------------------------------
// LayerNorm(h + attn_out). One block per row (512 cols), 128 threads.
// ---------------------------------------------------------------------------
__global__ __launch_bounds__(128) void ln_kernel(
    const float* __restrict__ h, const float* __restrict__ ao,
    const float* __restrict__ gamma, const float* __restrict__ beta,
    float* __restrict__ out)
{
    const int row = blockIdx.x;
    const int tid = threadIdx.x;
    __shared__ float red[4];

    const float* hp = h  + (size_t)row*512;
    const float* ap = ao + (size_t)row*512;
    float x[4];
    #pragma unroll
    for (int r = 0; r < 4; ++r) x[r] = hp[tid + r*128] + ap[tid + r*128];

    float s = (x[0] + x[1]) + (x[2] + x[3]);
    #pragma unroll
    for (int o = 16; o > 0; o >>= 1) s += __shfl_xor_sync(0xffffffffu, s, o);
    if ((tid & 31) == 0) red[tid >> 5] = s;
    __syncthreads();
    const float mu = (red[0] + red[1] + red[2] + red[3]) * (1.f/512.f);
    __syncthreads();

    float v = 0.f;
    #pragma unroll
    for (int r = 0; r < 4; ++r) { const float d = x[r] - mu; v = fmaf(d, d, v); }
    #pragma unroll
    for (int o = 16; o > 0; o >>= 1) v += __shfl_xor_sync(0xffffffffu, v, o);
    if ((tid & 31) == 0) red[tid >> 5] = v;
    __syncthreads();
    const float var  = (red[0] + red[1] + red[2] + red[3]) * (1.f/512.f);
    const float rstd = rsqrtf(var + LN_EPS);

    #pragma unroll
    for (int r = 0; r < 4; ++r) {
        const int col = tid + r*128;
        out[(size_t)row*512 + col] = (x[r] - mu)*rstd*gamma[col] + beta[col];
    }
}

// ---------------------------------------------------------------------------
extern "C" void kernel_launch(void* const* d_in, const int* in_sizes, int n_in,
                              void* d_out, int out_size)
{
    (void)in_sizes; (void)n_in; (void)out_size;
    const float* h     = (const float*)d_in[0];
    const float* Wq    = (const float*)d_in[1];
    const float* Wkv   = (const float*)d_in[2];
    const float* Wo    = (const float*)d_in[3];
    const float* gamma = (const float*)d_in[4];
    const float* beta  = (const float*)d_in[5];
    float* out = (float*)d_out;

    __half *h16, *wq16, *wkv16, *wo16, *Q16, *K16, *V16, *pkv, *AV;
    float *ckv, *cks, *pks, *AO;
    cudaGetSymbolAddress((void**)&h16,   g_h16);
    cudaGetSymbolAddress((void**)&wq16,  g_Wq16);
    cudaGetSymbolAddress((void**)&wkv16, g_Wkv16);
    cudaGetSymbolAddress((void**)&wo16,  g_Wo16);
    cudaGetSymbolAddress((void**)&Q16,   g_Q);
    cudaGetSymbolAddress((void**)&K16,   g_K);
    cudaGetSymbolAddress((void**)&V16,   g_V);
    cudaGetSymbolAddress((void**)&ckv,   g_ckv);
    cudaGetSymbolAddress((void**)&cks,   g_cks);
    cudaGetSymbolAddress((void**)&pkv,   g_pkv);
    cudaGetSymbolAddress((void**)&pks,   g_pks);
    cudaGetSymbolAddress((void**)&AV,    g_AV);
    cudaGetSymbolAddress((void**)&AO,    g_AO);

    constexpr int GEMM_SMEM = 3 * (128*80 + 32*272);   // 56832 bytes

    cudaFuncSetAttribute(gemm_mma<0>, cudaFuncAttributeMaxDynamicSharedMemorySize, GEMM_SMEM);
    cudaFuncSetAttribute(gemm_mma<1>, cudaFuncAttributeMaxDynamicSharedMemorySize, GEMM_SMEM);
    cudaFuncSetAttribute(gemm_mma<2>, cudaFuncAttributeMaxDynamicSharedMemorySize, GEMM_SMEM);
    cudaFuncSetAttribute(attn_kernel, cudaFuncAttributeMaxDynamicSharedMemorySize, ATTN_SMEM_BYTES);

    // 0. one fused fp32 -> fp16 conversion launch
    convert_all_kernel<<<3072, 256>>>(h, Wq, Wkv, Wo, h16, wq16, wkv16, wo16);

    // 1. Q = elu1(h @ Wq) -> fp16
    gemm_mma<1><<<dim3(4, 32), 256, GEMM_SMEM>>>(h16, wq16, nullptr, Q16, nullptr, 512, 512);
    // 2. KV = h @ Wkv -> K (elu1), V fp16
    gemm_mma<2><<<dim3(8, 32), 256, GEMM_SMEM>>>(h16, wkv16, nullptr, K16, V16, 1024, 512);

    // 3. chunked linear attention
    chunk_kv_kernel<<<dim3(NCHUNK, NBH), 256>>>(K16, V16, ckv, cks);
    prefix_kernel<<<dim3(NBH, 16), 256>>>(ckv, cks, pkv, pks);
    attn_kernel<<<dim3(NCHUNK, NBH), 256, ATTN_SMEM_BYTES>>>(Q16, K16, V16, pkv, pks, AV);

    // 4. attn_out = attn_vec @ Wo (fp32 out)
    gemm_mma<0><<<dim3(4, 32), 256, GEMM_SMEM>>>(AV, wo16, AO, nullptr, nullptr, 512, 512);

    // 5. out = LayerNorm(h + attn_out)
    ln_kernel<<<NROWS, 128>>>(h, AO, gamma, beta, out);
}

// round 6
// speedup vs baseline: 4.5547x; 1.5464x over previous
#include <cuda_runtime.h>
#include <cuda_fp16.h>
#include <cstdint>
#include <math.h>

// Problem constants
#define S_LEN   2048
#define BATCH   2
#define DMODEL  512
#define NHEAD   8
#define DHEAD   64
#define NROWS   (S_LEN*BATCH)        // 4096
#define CHUNK   128
#define NCHUNK  (S_LEN/CHUNK)        // 16
#define NBH     (BATCH*NHEAD)        // 16
#define ATT_SCALE 0.125f
#define ATT_EPS   1e-5f
#define LN_EPS    1e-5f

// ---------------------------------------------------------------------------
// PTX helpers — arch-agnostic (plain sm_103 target: no tcgen05)
// ---------------------------------------------------------------------------
__device__ __forceinline__ uint32_t smem_u32(const void* p) {
    uint32_t a;
    asm("{ .reg .u64 t; cvta.to.shared.u64 t, %1; cvt.u32.u64 %0, t; }"
        : "=r"(a) : "l"(p));
    return a;
}

#define LDSM4(r, addr) \
    asm volatile("ldmatrix.sync.aligned.m8n8.x4.shared.b16 {%0,%1,%2,%3}, [%4];" \
        : "=r"((r)[0]), "=r"((r)[1]), "=r"((r)[2]), "=r"((r)[3]) : "r"(addr))

#define LDSM4T(r, addr) \
    asm volatile("ldmatrix.sync.aligned.m8n8.x4.trans.shared.b16 {%0,%1,%2,%3}, [%4];" \
        : "=r"((r)[0]), "=r"((r)[1]), "=r"((r)[2]), "=r"((r)[3]) : "r"(addr))

#define MMA_F16(d, a, b) \
    asm volatile("mma.sync.aligned.m16n8k16.row.col.f32.f16.f16.f32 " \
        "{%0,%1,%2,%3}, {%4,%5,%6,%7}, {%8,%9}, {%0,%1,%2,%3};" \
        : "+f"((d)[0]), "+f"((d)[1]), "+f"((d)[2]), "+f"((d)[3]) \
        : "r"((a)[0]), "r"((a)[1]), "r"((a)[2]), "r"((a)[3]), \
          "r"((b)[0]), "r"((b)[1]))

#define CP_ASYNC16(sdst, gsrc) \
    asm volatile("cp.async.cg.shared.global [%0], [%1], 16;" \
        :: "r"(sdst), "l"(gsrc) : "memory")
#define CP_COMMIT() asm volatile("cp.async.commit_group;" ::: "memory")
#define CP_WAIT2()  asm volatile("cp.async.wait_group 2;" ::: "memory")

// ---------------------------------------------------------------------------
// Scratch (static device globals — no allocation allowed)
// ---------------------------------------------------------------------------
__device__ __half g_h16 [NROWS*DMODEL];
__device__ __half g_Wq16 [512*512];
__device__ __half g_Wkv16[512*1024];
__device__ __half g_Wo16 [512*512];

__device__ __half g_Q[NROWS*DMODEL];
__device__ __half g_K[NROWS*DMODEL];
__device__ __half g_V[NROWS*DMODEL];

__device__ float g_ckv[NBH*NCHUNK*DHEAD*DHEAD];
__device__ float g_cks[NBH*NCHUNK*DHEAD];
__device__ __half g_pkv[NBH*NCHUNK*DHEAD*DHEAD];
__device__ float g_pks[NBH*NCHUNK*DHEAD];

__device__ __half g_AV[NROWS*DMODEL];
__device__ float  g_AO[NROWS*DMODEL];

__device__ __forceinline__ float elu1(float x) {
    return x > 0.f ? x + 1.f : expf(x);
}

// ---------------------------------------------------------------------------
// Fused: convert all four fp32 tensors to fp16 in ONE launch.
// ---------------------------------------------------------------------------
__global__ __launch_bounds__(256) void convert_all_kernel(
    const float* __restrict__ h,  const float* __restrict__ Wq,
    const float* __restrict__ Wkv, const float* __restrict__ Wo,
    __half* __restrict__ h16, __half* __restrict__ wq16,
    __half* __restrict__ wkv16, __half* __restrict__ wo16)
{
    const int bid = blockIdx.x;
    const float* src; __half* dst; int i;
    if (bid < 2048)      { src = h;   dst = h16;   i = bid*256 + threadIdx.x; }
    else if (bid < 2304) { src = Wq;  dst = wq16;  i = (bid-2048)*256 + threadIdx.x; }
    else if (bid < 2816) { src = Wkv; dst = wkv16; i = (bid-2304)*256 + threadIdx.x; }
    else                 { src = Wo;  dst = wo16;  i = (bid-2816)*256 + threadIdx.x; }
    float4 v = ((const float4*)src)[i];
    __half2 p0; p0.x = __float2half_rn(v.x); p0.y = __float2half_rn(v.y);
    __half2 p1; p1.x = __float2half_rn(v.z); p1.y = __float2half_rn(v.w);
    ((__half2*)dst)[2*i]   = p0;
    ((__half2*)dst)[2*i+1] = p1;
}

// ---------------------------------------------------------------------------
// Single-term fp16 mma.sync GEMM: C[M,N] = A[M,K] @ W[K,N]  (W row-major)
// MODE 0: fp32 out  1: elu+1 -> D1 fp16  2: col<512 elu+1 -> D1, else -> D2
// ---------------------------------------------------------------------------
template<int MODE>
__global__ __launch_bounds__(256, 1) void gemm_mma(
    const __half* __restrict__ A, const __half* __restrict__ B,
    float* __restrict__ C, __half* __restrict__ D1, __half* __restrict__ D2,
    int N, int K)
{
    extern __shared__ char smem[];
    constexpr uint32_t TILEA = 128*80;
    constexpr uint32_t TILEB = 32*272;
    constexpr uint32_t BUFB  = TILEA + TILEB;

    const int tid = threadIdx.x;
    const int wid = tid >> 5, lane = tid & 31;
    const int m0 = blockIdx.y*128, n0 = blockIdx.x*128;
    const int warp_m = wid >> 2, warp_n = wid & 3;
    const uint32_t smb = smem_u32(smem);

    auto issue_chunk = [&](int kt, int buf) {
        const uint32_t sbase = smb + (uint32_t)buf*BUFB;
        #pragma unroll
        for (int half_ = 0; half_ < 2; ++half_) {
            const int idx = tid + half_*256;
            const int ar = idx >> 2, ac = idx & 3;
            const uint32_t asoff = (uint32_t)(ar*80 + ac*16);
            const size_t ga = (size_t)(m0 + ar)*K + (size_t)kt*32 + ac*8;
            CP_ASYNC16(sbase + asoff, A + ga);
            const int br = idx >> 4, bc = idx & 15;
            const uint32_t bsoff = (uint32_t)(br*272 + bc*16);
            const size_t gb = (size_t)(kt*32 + br)*N + n0 + bc*8;
            CP_ASYNC16(sbase + TILEA + bsoff, B + gb);
        }
        CP_COMMIT();
    };

    float d[4][4][4];
    #pragma unroll
    for (int mt = 0; mt < 4; ++mt)
        #pragma unroll
        for (int nt = 0; nt < 4; ++nt)
            #pragma unroll
            for (int e = 0; e < 4; ++e) d[mt][nt][e] = 0.f;

    const int NT = K >> 5;
    issue_chunk(0, 0);
    issue_chunk(1, 1);
    issue_chunk(2, 2);

    for (int kt = 0; kt < NT; ++kt) {
        CP_WAIT2();
        __syncthreads();
        const int buf = kt % 3;
        const uint32_t sA = smb + (uint32_t)buf*BUFB;
        const uint32_t sB = sA + TILEA;

        #pragma unroll
        for (int k16 = 0; k16 < 2; ++k16) {
            uint32_t a[4][4];
            #pragma unroll
            for (int mt = 0; mt < 4; ++mt) {
                const uint32_t r = warp_m*64 + mt*16 + (lane & 15);
                LDSM4(a[mt], sA + r*80 + k16*32 + (lane >> 4)*16);
            }
            uint32_t bfr[4][2];
            #pragma unroll
            for (int p = 0; p < 2; ++p) {
                const uint32_t addr = sB + (k16*16 + (lane & 15))*272
                                    + (warp_n*32 + p*16 + (lane >> 4)*8)*2;
                uint32_t t[4];
                LDSM4T(t, addr);
                bfr[2*p][0] = t[0]; bfr[2*p][1] = t[1];
                bfr[2*p+1][0] = t[2]; bfr[2*p+1][1] = t[3];
            }
            #pragma unroll
            for (int mt = 0; mt < 4; ++mt)
                #pragma unroll
                for (int nt = 0; nt < 4; ++nt)
                    MMA_F16(d[mt][nt], a[mt], bfr[nt]);
        }
        __syncthreads();
        if (kt + 3 < NT) issue_chunk(kt + 3, buf);
    }

    const int mb = m0 + warp_m*64;
    const int qr = lane >> 2, qc = (lane & 3)*2;
    #pragma unroll
    for (int mt = 0; mt < 4; ++mt) {
        const int r0 = mb + mt*16 + qr, r1 = r0 + 8;
        #pragma unroll
        for (int nt = 0; nt < 4; ++nt) {
            const int n = n0 + warp_n*32 + nt*8 + qc;
            float v0 = d[mt][nt][0], v1 = d[mt][nt][1];
            float v2 = d[mt][nt][2], v3 = d[mt][nt][3];
            if (MODE == 0) {
                float2 p0; p0.x = v0; p0.y = v1;
                float2 p1; p1.x = v2; p1.y = v3;
                *(float2*)&C[(size_t)r0*N + n] = p0;
                *(float2*)&C[(size_t)r1*N + n] = p1;
            } else {
                __half* dst; int col; bool do_elu;
                if (MODE == 1) { dst = D1; col = n; do_elu = true; }
                else if (n0 < 512) { dst = D1; col = n; do_elu = true; }
                else { dst = D2; col = n - 512; do_elu = false; }
                if (do_elu) { v0 = elu1(v0); v1 = elu1(v1); v2 = elu1(v2); v3 = elu1(v3); }
                __half2 p0; p0.x = __float2half_rn(v0); p0.y = __float2half_rn(v1);
                __half2 p1; p1.x = __float2half_rn(v2); p1.y = __float2half_rn(v3);
                *(__half2*)&dst[(size_t)r0*512 + col] = p0;
                *(__half2*)&dst[(size_t)r1*512 + col] = p1;
            }
        }
    }
}

// ---------------------------------------------------------------------------
// Tensor-core chunk KV: ckv[64,64] = K_tile^T @ V_tile  (K=128 j-rows).
// grid (NCHUNK, NBH), 128 threads (4 warps); warp w -> d rows [16w,16w+16).
// A = K^T via trans-ldmatrix from K[j][d]; B = V via trans-ldmatrix (proven).
// ---------------------------------------------------------------------------
__global__ __launch_bounds__(128) void chunk_kv_kernel(
    const __half* __restrict__ K16, const __half* __restrict__ V16,
    float* __restrict__ ckv, float* __restrict__ cks)
{
    __shared__ __align__(16) char sk[128*144];
    __shared__ __align__(16) char sv[128*144];

    const int c  = blockIdx.x, bh = blockIdx.y;
    const int b  = bh >> 3, hh = bh & 7;
    const int tid = threadIdx.x, wid = tid >> 5, lane = tid & 31;

    // load K,V tiles [128 j][64 d] fp16, pitch 144B
    {
        const __half2* K2 = (const __half2*)K16;
        const __half2* V2 = (const __half2*)V16;
        #pragma unroll
        for (int t = 0; t < 32; ++t) {
            const int u = tid + t*128;                 // 0..4095
            const int row = u >> 5, c2 = u & 31;
            const size_t g = (size_t)((c*CHUNK + row)*BATCH + b)*256 + hh*32 + c2;
            *(__half2*)(sk + row*144 + c2*4) = K2[g];
            *(__half2*)(sv + row*144 + c2*4) = V2[g];
        }
    }
    __syncthreads();

    const uint32_t skb = smem_u32(sk), svb = smem_u32(sv);
    const int m0 = wid*16;                             // d-row base for warp

    float acc[8][4];
    #pragma unroll
    for (int nt = 0; nt < 8; ++nt)
        #pragma unroll
        for (int e = 0; e < 4; ++e) acc[nt][e] = 0.f;

    #pragma unroll
    for (int ks = 0; ks < 8; ++ks) {                   // k = j, 8 steps of 16
        uint32_t a[4];
        {   // A[m=d][k=j] from storage K[j][d] via trans
            const uint32_t arow = ks*16 + (lane & 7) + ((lane & 16) >> 1);
            LDSM4T(a, skb + arow*144 + (m0 + (lane & 8))*2);
        }
        #pragma unroll
        for (int p = 0; p < 4; ++p) {                  // 8 n-tiles (pairs)
            uint32_t t[4];
            const uint32_t baddr = svb + (ks*16 + (lane & 15))*144
                                 + (p*16 + (lane >> 4)*8)*2;
            LDSM4T(t, baddr);
            uint32_t b0[2] = { t[0], t[1] };
            uint32_t b1[2] = { t[2], t[3] };
            MMA_F16(acc[2*p],     a, b0);
            MMA_F16(acc[2*p + 1], a, b1);
        }
    }

    // write ckv
    const int qr = lane >> 2, qc = (lane & 3)*2;
    float* outp = ckv + (((size_t)bh*NCHUNK + c) << 12);
    #pragma unroll
    for (int nt = 0; nt < 8; ++nt) {
        const int e = nt*8 + qc;
        const int d0 = m0 + qr, d1 = d0 + 8;
        float2 p0; p0.x = acc[nt][0]; p0.y = acc[nt][1];
        float2 p1; p1.x = acc[nt][2]; p1.y = acc[nt][3];
        *(float2*)&outp[d0*64 + e] = p0;
        *(float2*)&outp[d1*64 + e] = p1;
    }

    // ksum: cks[d] = sum_j K[j][d]
    if (tid < 64) {
        float s = 0.f;
        #pragma unroll 16
        for (int j = 0; j < 128; ++j)
            s += __half2float(*(const __half*)(sk + j*144 + tid*2));
        cks[(bh*NCHUNK + c)*64 + tid] = s;
    }
}

// ---------------------------------------------------------------------------
// Exclusive prefix over chunks — St out as fp16. grid (NBH, 16), 256 threads.
// ---------------------------------------------------------------------------
__global__ __launch_bounds__(256) void prefix_kernel(
    const float* __restrict__ ckv, const float* __restrict__ cks,
    __half* __restrict__ pkv, float* __restrict__ pks)
{
    const int bh  = blockIdx.x;
    const int idx = blockIdx.y*256 + threadIdx.x;
    const size_t base = ((size_t)bh*NCHUNK) << 12;

    float v[NCHUNK];
    #pragma unroll
    for (int c = 0; c < NCHUNK; ++c) v[c] = ckv[base + ((size_t)c << 12) + idx];
    float acc = 0.f;
    #pragma unroll
    for (int c = 0; c < NCHUNK; ++c) {
        pkv[base + ((size_t)c << 12) + idx] = __float2half_rn(acc);
        acc += v[c];
    }
    if (blockIdx.y == 0 && threadIdx.x < 64) {
        const int t = threadIdx.x;
        float s[NCHUNK];
        #pragma unroll
        for (int c = 0; c < NCHUNK; ++c) s[c] = cks[(bh*NCHUNK + c)*64 + t];
        float a = 0.f;
        #pragma unroll
        for (int c = 0; c < NCHUNK; ++c) {
            pks[(bh*NCHUNK + c)*64 + t] = a;
            a += s[c];
        }
    }
}

// ---------------------------------------------------------------------------
// Tensor-core chunked linear attention, fp16. grid (NCHUNK, NBH), 256 thr.
// ---------------------------------------------------------------------------
#define A_Q    0u
#define A_K    18432u
#define A_V    36864u
#define A_ST   55296u
#define A_SC   64512u
#define A_KP   99328u
#define A_DLOC 99584u
#define ATTN_SMEM_BYTES 100096

__global__ __launch_bounds__(256, 2) void attn_kernel(
    const __half* __restrict__ Q16, const __half* __restrict__ K16,
    const __half* __restrict__ V16, const __half* __restrict__ pkv,
    const float* __restrict__ pks, __half* __restrict__ AV)
{
    extern __shared__ char sm[];
    const uint32_t smb = smem_u32(sm);

    const int c  = blockIdx.x, bh = blockIdx.y;
    const int b  = bh >> 3, hh = bh & 7;
    const int tid = threadIdx.x;
    const int wid = tid >> 5, lane = tid & 31;
    const int warp_m = wid >> 2, warp_n = wid & 3;

    {
        const __half2* Q2 = (const __half2*)Q16;
        const __half2* K2 = (const __half2*)K16;
        const __half2* V2 = (const __half2*)V16;
        #pragma unroll
        for (int t = 0; t < 16; ++t) {
            const int u = tid + t*256;
            const int row = u >> 5, c2 = u & 31;
            const size_t g = (size_t)((c*CHUNK + row)*BATCH + b)*256 + hh*32 + c2;
            const uint32_t so = row*144 + c2*4;
            *(__half2*)(sm + A_Q + so) = Q2[g];
            *(__half2*)(sm + A_K + so) = K2[g];
            *(__half2*)(sm + A_V + so) = V2[g];
        }
        const __half2* S2 = (const __half2*)pkv;
        const size_t sbase = ((size_t)(bh*NCHUNK + c))*2048;
        #pragma unroll
        for (int t = 0; t < 8; ++t) {
            const int u = tid + t*256;
            const int dd = u >> 5, e2 = u & 31;
            *(__half2*)(sm + A_ST + dd*144 + e2*4) = S2[sbase + u];
        }
        if (tid < 64)
            ((float*)(sm + A_KP))[tid] = pks[(bh*NCHUNK + c)*64 + tid];
    }
    __syncthreads();

    const int qr = lane >> 2, qc = (lane & 3)*2;

    // ---- Stage 1: S = Q @ K^T, masked -> Ssc fp16 ----
    {
        float d1[4][4][4];
        #pragma unroll
        for (int mt = 0; mt < 4; ++mt)
            #pragma unroll
            for (int nt = 0; nt < 4; ++nt)
                #pragma unroll
                for (int e = 0; e < 4; ++e) d1[mt][nt][e] = 0.f;

        #pragma unroll
        for (int ks = 0; ks < 4; ++ks) {
            uint32_t a[4][4];
            #pragma unroll
            for (int mt = 0; mt < 4; ++mt) {
                const uint32_t r = warp_m*64 + mt*16 + (lane & 15);
                LDSM4(a[mt], smb + A_Q + r*144 + ks*32 + (lane >> 4)*16);
            }
            uint32_t bf[4][2];
            #pragma unroll
            for (int p = 0; p < 2; ++p) {
                const uint32_t r = warp_n*32 + p*16 + (lane & 7) + ((lane & 16) >> 1);
                uint32_t t[4];
                LDSM4(t, smb + A_K + r*144 + ks*32 + (lane & 8)*2);
                bf[2*p][0]=t[0]; bf[2*p][1]=t[1]; bf[2*p+1][0]=t[2]; bf[2*p+1][1]=t[3];
            }
            #pragma unroll
            for (int mt = 0; mt < 4; ++mt)
                #pragma unroll
                for (int nt = 0; nt < 4; ++nt)
                    MMA_F16(d1[mt][nt], a[mt], bf[nt]);
        }
        #pragma unroll
        for (int mt = 0; mt < 4; ++mt) {
            const int i0 = warp_m*64 + mt*16 + qr, i1 = i0 + 8;
            #pragma unroll
            for (int nt = 0; nt < 4; ++nt) {
                const int j = warp_n*32 + nt*8 + qc;
                float v0 = (j   <= i0) ? d1[mt][nt][0] : 0.f;
                float v1 = (j+1 <= i0) ? d1[mt][nt][1] : 0.f;
                float v2 = (j   <= i1) ? d1[mt][nt][2] : 0.f;
                float v3 = (j+1 <= i1) ? d1[mt][nt][3] : 0.f;
                __half2 p0; p0.x = __float2half_rn(v0); p0.y = __float2half_rn(v1);
                __half2 p1; p1.x = __float2half_rn(v2); p1.y = __float2half_rn(v3);
                *(__half2*)(sm + A_SC + i0*272 + j*2) = p0;
                *(__half2*)(sm + A_SC + i1*272 + j*2) = p1;
            }
        }
    }
    __syncthreads();

    // ---- Stage 2: denominators ----
    {
        const int i = tid >> 1, half_ = tid & 1;
        float s = 0.f;
        const char* rh = sm + A_SC + i*272 + half_*128;
        #pragma unroll
        for (int j2 = 0; j2 < 32; ++j2) {
            __half2 ph = *(const __half2*)(rh + j2*4);
            s += __half2float(ph.x) + __half2float(ph.y);
        }
        const float* kp = (const float*)(sm + A_KP);
        const char* qh = sm + A_Q + i*144 + half_*64;
        #pragma unroll
        for (int k2 = 0; k2 < 16; ++k2) {
            __half2 ph = *(const __half2*)(qh + k2*4);
            const int k = half_*32 + k2*2;
            s = fmaf(__half2float(ph.x), kp[k],   s);
            s = fmaf(__half2float(ph.y), kp[k+1], s);
        }
        s += __shfl_xor_sync(0xffffffffu, s, 1);
        if (half_ == 0)
            ((float*)(sm + A_DLOC))[i] = 1.f / (s*ATT_SCALE + ATT_EPS);
    }
    __syncthreads();

    // ---- Stage 3: O = Ssc @ V + Q @ St ----
    {
        float d3[4][2][4];
        #pragma unroll
        for (int mt = 0; mt < 4; ++mt)
            #pragma unroll
            for (int nt = 0; nt < 2; ++nt)
                #pragma unroll
                for (int e = 0; e < 4; ++e) d3[mt][nt][e] = 0.f;

        #pragma unroll
        for (int ks = 0; ks < 8; ++ks) {
            uint32_t a[4][4];
            #pragma unroll
            for (int mt = 0; mt < 4; ++mt) {
                const uint32_t r = warp_m*64 + mt*16 + (lane & 15);
                LDSM4(a[mt], smb + A_SC + r*272 + ks*32 + (lane >> 4)*16);
            }
            uint32_t bf[2][2];
            {
                const uint32_t addr = smb + A_V + (ks*16 + (lane & 15))*144
                                    + (warp_n*16 + (lane >> 4)*8)*2;
                uint32_t t[4];
                LDSM4T(t, addr);
                bf[0][0]=t[0]; bf[0][1]=t[1]; bf[1][0]=t[2]; bf[1][1]=t[3];
            }
            #pragma unroll
            for (int mt = 0; mt < 4; ++mt)
                #pragma unroll
                for (int nt = 0; nt < 2; ++nt)
                    MMA_F16(d3[mt][nt], a[mt], bf[nt]);
        }
        #pragma unroll
        for (int ks = 0; ks < 4; ++ks) {
            uint32_t a[4][4];
            #pragma unroll
            for (int mt = 0; mt < 4; ++mt) {
                const uint32_t r = warp_m*64 + mt*16 + (lane & 15);
                LDSM4(a[mt], smb + A_Q + r*144 + ks*32 + (lane >> 4)*16);
            }
            uint32_t bf[2][2];
            {
                const uint32_t addr = smb + A_ST + (ks*16 + (lane & 15))*144
                                    + (warp_n*16 + (lane >> 4)*8)*2;
                uint32_t t[4];
                LDSM4T(t, addr);
                bf[0][0]=t[0]; bf[0][1]=t[1]; bf[1][0]=t[2]; bf[1][1]=t[3];
            }
            #pragma unroll
            for (int mt = 0; mt < 4; ++mt)
                #pragma unroll
                for (int nt = 0; nt < 2; ++nt)
                    MMA_F16(d3[mt][nt], a[mt], bf[nt]);
        }

        const float* dloc = (const float*)(sm + A_DLOC);
        __half2* AV2 = (__half2*)AV;
        #pragma unroll
        for (int mt = 0; mt < 4; ++mt) {
            const int i0 = warp_m*64 + mt*16 + qr, i1 = i0 + 8;
            const float sc0 = ATT_SCALE * dloc[i0];
            const float sc1 = ATT_SCALE * dloc[i1];
            const size_t g0 = (size_t)((c*CHUNK + i0)*BATCH + b)*256 + hh*32;
            const size_t g1 = (size_t)((c*CHUNK + i1)*BATCH + b)*256 + hh*32;
            #pragma unroll
            for (int nt = 0; nt < 2; ++nt) {
                const int n = warp_n*16 + nt*8 + qc;
                __half2 p0, p1;
                p0.x = __float2half_rn(d3[mt][nt][0]*sc0);
                p0.y = __float2half_rn(d3[mt][nt][1]*sc0);
                p1.x = __float2half_rn(d3[mt][nt][2]*sc1);
                p1.y = __float2half_rn(d3[mt][nt][3]*sc1);
                AV2[g0 + (n >> 1)] = p0;
                AV2[g1 + (n >> 1)] = p1;
            }
        }
    }
}

// ---------------------------------------------------------------------------
// LayerNorm(h + attn_out). One block per row (512 cols), 128 threads.
// ---------------------------------------------------------------------------
__global__ __launch_bounds__(128) void ln_kernel(
    const float* __restrict__ h, const float* __restrict__ ao,
    const float* __restrict__ gamma, const float* __restrict__ beta,
    float* __restrict__ out)
{
    const int row = blockIdx.x;
    const int tid = threadIdx.x;
    __shared__ float red[4];

    const float* hp = h  + (size_t)row*512;
    const float* ap = ao + (size_t)row*512;
    float x[4];
    #pragma unroll
    for (int r = 0; r < 4; ++r) x[r] = hp[tid + r*128] + ap[tid + r*128];

    float s = (x[0] + x[1]) + (x[2] + x[3]);
    #pragma unroll
    for (int o = 16; o > 0; o >>= 1) s += __shfl_xor_sync(0xffffffffu, s, o);
    if ((tid & 31) == 0) red[tid >> 5] = s;
    __syncthreads();
    const float mu = (red[0] + red[1] + red[2] + red[3]) * (1.f/512.f);
    __syncthreads();

    float v = 0.f;
    #pragma unroll
    for (int r = 0; r < 4; ++r) { const float d = x[r] - mu; v = fmaf(d, d, v); }
    #pragma unroll
    for (int o = 16; o > 0; o >>= 1) v += __shfl_xor_sync(0xffffffffu, v, o);
    if ((tid & 31) == 0) red[tid >> 5] = v;
    __syncthreads();
    const float var  = (red[0] + red[1] + red[2] + red[3]) * (1.f/512.f);
    const float rstd = rsqrtf(var + LN_EPS);

    #pragma unroll
    for (int r = 0; r < 4; ++r) {
        const int col = tid + r*128;
        out[(size_t)row*512 + col] = (x[r] - mu)*rstd*gamma[col] + beta[col];
    }
}

// ---------------------------------------------------------------------------
extern "C" void kernel_launch(void* const* d_in, const int* in_sizes, int n_in,
                              void* d_out, int out_size)
{
    (void)in_sizes; (void)n_in; (void)out_size;
    const float* h     = (const float*)d_in[0];
    const float* Wq    = (const float*)d_in[1];
    const float* Wkv   = (const float*)d_in[2];
    const float* Wo    = (const float*)d_in[3];
    const float* gamma = (const float*)d_in[4];
    const float* beta  = (const float*)d_in[5];
    float* out = (float*)d_out;

    __half *h16, *wq16, *wkv16, *wo16, *Q16, *K16, *V16, *pkv, *AV;
    float *ckv, *cks, *pks, *AO;
    cudaGetSymbolAddress((void**)&h16,   g_h16);
    cudaGetSymbolAddress((void**)&wq16,  g_Wq16);
    cudaGetSymbolAddress((void**)&wkv16, g_Wkv16);
    cudaGetSymbolAddress((void**)&wo16,  g_Wo16);
    cudaGetSymbolAddress((void**)&Q16,   g_Q);
    cudaGetSymbolAddress((void**)&K16,   g_K);
    cudaGetSymbolAddress((void**)&V16,   g_V);
    cudaGetSymbolAddress((void**)&ckv,   g_ckv);
    cudaGetSymbolAddress((void**)&cks,   g_cks);
    cudaGetSymbolAddress((void**)&pkv,   g_pkv);
    cudaGetSymbolAddress((void**)&pks,   g_pks);
    cudaGetSymbolAddress((void**)&AV,    g_AV);
    cudaGetSymbolAddress((void**)&AO,    g_AO);

    constexpr int GEMM_SMEM = 3 * (128*80 + 32*272);

    cudaFuncSetAttribute(gemm_mma<0>, cudaFuncAttributeMaxDynamicSharedMemorySize, GEMM_SMEM);
    cudaFuncSetAttribute(gemm_mma<1>, cudaFuncAttributeMaxDynamicSharedMemorySize, GEMM_SMEM);
    cudaFuncSetAttribute(gemm_mma<2>, cudaFuncAttributeMaxDynamicSharedMemorySize, GEMM_SMEM);
    cudaFuncSetAttribute(attn_kernel, cudaFuncAttributeMaxDynamicSharedMemorySize, ATTN_SMEM_BYTES);

    convert_all_kernel<<<3072, 256>>>(h, Wq, Wkv, Wo, h16, wq16, wkv16, wo16);

    gemm_mma<1><<<dim3(4, 32), 256, GEMM_SMEM>>>(h16, wq16, nullptr, Q16, nullptr, 512, 512);
    gemm_mma<2><<<dim3(8, 32), 256, GEMM_SMEM>>>(h16, wkv16, nullptr, K16, V16, 1024, 512);

    chunk_kv_kernel<<<dim3(NCHUNK, NBH), 128>>>(K16, V16, ckv, cks);
    prefix_kernel<<<dim3(NBH, 16), 256>>>(ckv, cks, pkv, pks);
    attn_kernel<<<dim3(NCHUNK, NBH), 256, ATTN_SMEM_BYTES>>>(Q16, K16, V16, pkv, pks, AV);

    gemm_mma<0><<<dim3(4, 32), 256, GEMM_SMEM>>>(AV, wo16, AO, nullptr, nullptr, 512, 512);

    ln_kernel<<<NROWS, 128>>>(h, AO, gamma, beta, out);
}

// round 7
// speedup vs baseline: 5.5050x; 1.2086x over previous
#include <cuda_runtime.h>
#include <cuda_fp16.h>
#include <cstdint>
#include <math.h>

// Problem constants
#define S_LEN   2048
#define BATCH   2
#define DMODEL  512
#define NHEAD   8
#define DHEAD   64
#define NROWS   (S_LEN*BATCH)        // 4096
#define CHUNK   128
#define NCHUNK  (S_LEN/CHUNK)        // 16
#define NBH     (BATCH*NHEAD)        // 16
#define ATT_SCALE 0.125f
#define ATT_EPS   1e-5f
#define LN_EPS    1e-5f

// ---------------------------------------------------------------------------
// PTX helpers — arch-agnostic (plain sm_103 target: no tcgen05)
// ---------------------------------------------------------------------------
__device__ __forceinline__ uint32_t smem_u32(const void* p) {
    uint32_t a;
    asm("{ .reg .u64 t; cvta.to.shared.u64 t, %1; cvt.u32.u64 %0, t; }"
        : "=r"(a) : "l"(p));
    return a;
}

#define LDSM4(r, addr) \
    asm volatile("ldmatrix.sync.aligned.m8n8.x4.shared.b16 {%0,%1,%2,%3}, [%4];" \
        : "=r"((r)[0]), "=r"((r)[1]), "=r"((r)[2]), "=r"((r)[3]) : "r"(addr))

#define LDSM4T(r, addr) \
    asm volatile("ldmatrix.sync.aligned.m8n8.x4.trans.shared.b16 {%0,%1,%2,%3}, [%4];" \
        : "=r"((r)[0]), "=r"((r)[1]), "=r"((r)[2]), "=r"((r)[3]) : "r"(addr))

#define MMA_F16(d, a, b) \
    asm volatile("mma.sync.aligned.m16n8k16.row.col.f32.f16.f16.f32 " \
        "{%0,%1,%2,%3}, {%4,%5,%6,%7}, {%8,%9}, {%0,%1,%2,%3};" \
        : "+f"((d)[0]), "+f"((d)[1]), "+f"((d)[2]), "+f"((d)[3]) \
        : "r"((a)[0]), "r"((a)[1]), "r"((a)[2]), "r"((a)[3]), \
          "r"((b)[0]), "r"((b)[1]))

#define CP_ASYNC16(sdst, gsrc) \
    asm volatile("cp.async.cg.shared.global [%0], [%1], 16;" \
        :: "r"(sdst), "l"(gsrc) : "memory")
#define CP_COMMIT() asm volatile("cp.async.commit_group;" ::: "memory")
#define CP_WAIT2()  asm volatile("cp.async.wait_group 2;" ::: "memory")
#define CP_WAIT0()  asm volatile("cp.async.wait_group 0;" ::: "memory")

// ---------------------------------------------------------------------------
// Scratch (static device globals — no allocation allowed)
// ---------------------------------------------------------------------------
__device__ __half g_h16 [NROWS*DMODEL];
__device__ __half g_Wq16 [512*512];
__device__ __half g_Wkv16[512*1024];
__device__ __half g_Wo16 [512*512];

__device__ __half g_Q[NROWS*DMODEL];
__device__ __half g_K[NROWS*DMODEL];
__device__ __half g_V[NROWS*DMODEL];

__device__ float g_ckv[NBH*NCHUNK*DHEAD*DHEAD];
__device__ float g_cks[NBH*NCHUNK*DHEAD];
__device__ __half g_pkv[NBH*NCHUNK*DHEAD*DHEAD];
__device__ float g_pks[NBH*NCHUNK*DHEAD];

__device__ __half g_AV[NROWS*DMODEL];
__device__ float  g_AO[NROWS*DMODEL];

__device__ __forceinline__ float elu1(float x) {
    return x > 0.f ? x + 1.f : expf(x);
}

// ---------------------------------------------------------------------------
// Fused: convert all four fp32 tensors to fp16 in ONE launch.
// ---------------------------------------------------------------------------
__global__ __launch_bounds__(256) void convert_all_kernel(
    const float* __restrict__ h,  const float* __restrict__ Wq,
    const float* __restrict__ Wkv, const float* __restrict__ Wo,
    __half* __restrict__ h16, __half* __restrict__ wq16,
    __half* __restrict__ wkv16, __half* __restrict__ wo16)
{
    const int bid = blockIdx.x;
    const float* src; __half* dst; int i;
    if (bid < 2048)      { src = h;   dst = h16;   i = bid*256 + threadIdx.x; }
    else if (bid < 2304) { src = Wq;  dst = wq16;  i = (bid-2048)*256 + threadIdx.x; }
    else if (bid < 2816) { src = Wkv; dst = wkv16; i = (bid-2304)*256 + threadIdx.x; }
    else                 { src = Wo;  dst = wo16;  i = (bid-2816)*256 + threadIdx.x; }
    float4 v = ((const float4*)src)[i];
    __half2 p0; p0.x = __float2half_rn(v.x); p0.y = __float2half_rn(v.y);
    __half2 p1; p1.x = __float2half_rn(v.z); p1.y = __float2half_rn(v.w);
    ((__half2*)dst)[2*i]   = p0;
    ((__half2*)dst)[2*i+1] = p1;
}

// ---------------------------------------------------------------------------
// Merged Q + KV projection GEMM (K=512, one launch, 2 CTA/SM target).
// grid (12, 32): bx<4 -> Q tile (Wq, elu); bx>=4 -> KV tile (Wkv, split K/V).
// 128x128 CTA tile, 8 warps, 3-stage cp.async pipeline.
// ---------------------------------------------------------------------------
__global__ __launch_bounds__(256, 2) void qkv_gemm(
    const __half* __restrict__ A, const __half* __restrict__ Bq,
    const __half* __restrict__ Bkv,
    __half* __restrict__ Qo, __half* __restrict__ Ko, __half* __restrict__ Vo)
{
    extern __shared__ char smem[];
    constexpr uint32_t TILEA = 128*80;
    constexpr uint32_t TILEB = 32*272;
    constexpr uint32_t BUFB  = TILEA + TILEB;
    constexpr int K = 512, NT = 16;

    const int bx = blockIdx.x;
    const bool isQ = bx < 4;
    const __half* B = isQ ? Bq : Bkv;
    const int N  = isQ ? 512 : 1024;
    const int n0 = (isQ ? bx : bx - 4)*128;

    const int tid = threadIdx.x;
    const int wid = tid >> 5, lane = tid & 31;
    const int m0 = blockIdx.y*128;
    const int warp_m = wid >> 2, warp_n = wid & 3;
    const uint32_t smb = smem_u32(smem);

    auto issue_chunk = [&](int kt, int buf) {
        const uint32_t sbase = smb + (uint32_t)buf*BUFB;
        #pragma unroll
        for (int half_ = 0; half_ < 2; ++half_) {
            const int idx = tid + half_*256;
            const int ar = idx >> 2, ac = idx & 3;
            const uint32_t asoff = (uint32_t)(ar*80 + ac*16);
            const size_t ga = (size_t)(m0 + ar)*K + (size_t)kt*32 + ac*8;
            CP_ASYNC16(sbase + asoff, A + ga);
            const int br = idx >> 4, bc = idx & 15;
            const uint32_t bsoff = (uint32_t)(br*272 + bc*16);
            const size_t gb = (size_t)(kt*32 + br)*N + n0 + bc*8;
            CP_ASYNC16(sbase + TILEA + bsoff, B + gb);
        }
        CP_COMMIT();
    };

    float d[4][4][4];
    #pragma unroll
    for (int mt = 0; mt < 4; ++mt)
        #pragma unroll
        for (int nt = 0; nt < 4; ++nt)
            #pragma unroll
            for (int e = 0; e < 4; ++e) d[mt][nt][e] = 0.f;

    issue_chunk(0, 0);
    issue_chunk(1, 1);
    issue_chunk(2, 2);

    for (int kt = 0; kt < NT; ++kt) {
        CP_WAIT2();
        __syncthreads();
        const int buf = kt % 3;
        const uint32_t sA = smb + (uint32_t)buf*BUFB;
        const uint32_t sB = sA + TILEA;

        #pragma unroll
        for (int k16 = 0; k16 < 2; ++k16) {
            uint32_t a[4][4];
            #pragma unroll
            for (int mt = 0; mt < 4; ++mt) {
                const uint32_t r = warp_m*64 + mt*16 + (lane & 15);
                LDSM4(a[mt], sA + r*80 + k16*32 + (lane >> 4)*16);
            }
            uint32_t bfr[4][2];
            #pragma unroll
            for (int p = 0; p < 2; ++p) {
                const uint32_t addr = sB + (k16*16 + (lane & 15))*272
                                    + (warp_n*32 + p*16 + (lane >> 4)*8)*2;
                uint32_t t[4];
                LDSM4T(t, addr);
                bfr[2*p][0] = t[0]; bfr[2*p][1] = t[1];
                bfr[2*p+1][0] = t[2]; bfr[2*p+1][1] = t[3];
            }
            #pragma unroll
            for (int mt = 0; mt < 4; ++mt)
                #pragma unroll
                for (int nt = 0; nt < 4; ++nt)
                    MMA_F16(d[mt][nt], a[mt], bfr[nt]);
        }
        __syncthreads();
        if (kt + 3 < NT) issue_chunk(kt + 3, buf);
    }

    // Epilogue: whole 128-wide tile goes to one destination
    __half* dst = isQ ? Qo : ((n0 < 512) ? Ko : Vo);
    const int coloff = (!isQ && n0 >= 512) ? 512 : 0;
    const bool do_elu = isQ || (n0 < 512);

    const int mb = m0 + warp_m*64;
    const int qr = lane >> 2, qc = (lane & 3)*2;
    #pragma unroll
    for (int mt = 0; mt < 4; ++mt) {
        const int r0 = mb + mt*16 + qr, r1 = r0 + 8;
        #pragma unroll
        for (int nt = 0; nt < 4; ++nt) {
            const int n = n0 + warp_n*32 + nt*8 + qc;
            float v0 = d[mt][nt][0], v1 = d[mt][nt][1];
            float v2 = d[mt][nt][2], v3 = d[mt][nt][3];
            if (do_elu) { v0 = elu1(v0); v1 = elu1(v1); v2 = elu1(v2); v3 = elu1(v3); }
            __half2 p0; p0.x = __float2half_rn(v0); p0.y = __float2half_rn(v1);
            __half2 p1; p1.x = __float2half_rn(v2); p1.y = __float2half_rn(v3);
            const int col = n - coloff;
            *(__half2*)&dst[(size_t)r0*512 + col] = p0;
            *(__half2*)&dst[(size_t)r1*512 + col] = p1;
        }
    }
}

// ---------------------------------------------------------------------------
// Output-projection GEMM: AO[4096,512] = AV @ Wo (fp32 out), 128x128 tiles.
// ---------------------------------------------------------------------------
__global__ __launch_bounds__(256, 2) void wo_gemm(
    const __half* __restrict__ A, const __half* __restrict__ B,
    float* __restrict__ C)
{
    extern __shared__ char smem[];
    constexpr uint32_t TILEA = 128*80;
    constexpr uint32_t TILEB = 32*272;
    constexpr uint32_t BUFB  = TILEA + TILEB;
    constexpr int K = 512, N = 512, NT = 16;

    const int tid = threadIdx.x;
    const int wid = tid >> 5, lane = tid & 31;
    const int m0 = blockIdx.y*128, n0 = blockIdx.x*128;
    const int warp_m = wid >> 2, warp_n = wid & 3;
    const uint32_t smb = smem_u32(smem);

    auto issue_chunk = [&](int kt, int buf) {
        const uint32_t sbase = smb + (uint32_t)buf*BUFB;
        #pragma unroll
        for (int half_ = 0; half_ < 2; ++half_) {
            const int idx = tid + half_*256;
            const int ar = idx >> 2, ac = idx & 3;
            const size_t ga = (size_t)(m0 + ar)*K + (size_t)kt*32 + ac*8;
            CP_ASYNC16(sbase + (uint32_t)(ar*80 + ac*16), A + ga);
            const int br = idx >> 4, bc = idx & 15;
            const size_t gb = (size_t)(kt*32 + br)*N + n0 + bc*8;
            CP_ASYNC16(sbase + TILEA + (uint32_t)(br*272 + bc*16), B + gb);
        }
        CP_COMMIT();
    };

    float d[4][4][4];
    #pragma unroll
    for (int mt = 0; mt < 4; ++mt)
        #pragma unroll
        for (int nt = 0; nt < 4; ++nt)
            #pragma unroll
            for (int e = 0; e < 4; ++e) d[mt][nt][e] = 0.f;

    issue_chunk(0, 0);
    issue_chunk(1, 1);
    issue_chunk(2, 2);

    for (int kt = 0; kt < NT; ++kt) {
        CP_WAIT2();
        __syncthreads();
        const int buf = kt % 3;
        const uint32_t sA = smb + (uint32_t)buf*BUFB;
        const uint32_t sB = sA + TILEA;

        #pragma unroll
        for (int k16 = 0; k16 < 2; ++k16) {
            uint32_t a[4][4];
            #pragma unroll
            for (int mt = 0; mt < 4; ++mt) {
                const uint32_t r = warp_m*64 + mt*16 + (lane & 15);
                LDSM4(a[mt], sA + r*80 + k16*32 + (lane >> 4)*16);
            }
            uint32_t bfr[4][2];
            #pragma unroll
            for (int p = 0; p < 2; ++p) {
                const uint32_t addr = sB + (k16*16 + (lane & 15))*272
                                    + (warp_n*32 + p*16 + (lane >> 4)*8)*2;
                uint32_t t[4];
                LDSM4T(t, addr);
                bfr[2*p][0] = t[0]; bfr[2*p][1] = t[1];
                bfr[2*p+1][0] = t[2]; bfr[2*p+1][1] = t[3];
            }
            #pragma unroll
            for (int mt = 0; mt < 4; ++mt)
                #pragma unroll
                for (int nt = 0; nt < 4; ++nt)
                    MMA_F16(d[mt][nt], a[mt], bfr[nt]);
        }
        __syncthreads();
        if (kt + 3 < NT) issue_chunk(kt + 3, buf);
    }

    const int mb = m0 + warp_m*64;
    const int qr = lane >> 2, qc = (lane & 3)*2;
    #pragma unroll
    for (int mt = 0; mt < 4; ++mt) {
        const int r0 = mb + mt*16 + qr, r1 = r0 + 8;
        #pragma unroll
        for (int nt = 0; nt < 4; ++nt) {
            const int n = n0 + warp_n*32 + nt*8 + qc;
            float2 p0; p0.x = d[mt][nt][0]; p0.y = d[mt][nt][1];
            float2 p1; p1.x = d[mt][nt][2]; p1.y = d[mt][nt][3];
            *(float2*)&C[(size_t)r0*N + n] = p0;
            *(float2*)&C[(size_t)r1*N + n] = p1;
        }
    }
}

// ---------------------------------------------------------------------------
// Tensor-core chunk KV: ckv[64,64] = K_tile^T @ V_tile  (K=128 j-rows).
// grid (NCHUNK, NBH), 256 threads (8 warps): warp (wd,we) -> d[16wd..],
// e[32we..]. cp.async loads.
// ---------------------------------------------------------------------------
__global__ __launch_bounds__(256) void chunk_kv_kernel(
    const __half* __restrict__ K16, const __half* __restrict__ V16,
    float* __restrict__ ckv, float* __restrict__ cks)
{
    __shared__ __align__(16) char sk[128*144];
    __shared__ __align__(16) char sv[128*144];

    const int c  = blockIdx.x, bh = blockIdx.y;
    const int b  = bh >> 3, hh = bh & 7;
    const int tid = threadIdx.x, wid = tid >> 5, lane = tid & 31;
    const uint32_t skb = smem_u32(sk), svb = smem_u32(sv);

    // cp.async loads: per tensor 128 rows x 8 x 16B = 1024 transfers
    #pragma unroll
    for (int t = 0; t < 4; ++t) {
        const int u = tid + t*256;                     // 0..1023
        const int row = u >> 3, c16 = u & 7;
        const size_t g = (size_t)((c*CHUNK + row)*BATCH + b)*512 + hh*64 + c16*8;
        const uint32_t so = row*144 + c16*16;
        CP_ASYNC16(skb + so, K16 + g);
        CP_ASYNC16(svb + so, V16 + g);
    }
    CP_COMMIT();
    CP_WAIT0();
    __syncthreads();

    const int wd = wid >> 1, we = wid & 1;
    const int m0 = wd*16;                              // d-row base
    const int e0 = we*32;                              // e-col base

    float acc[4][4];
    #pragma unroll
    for (int nt = 0; nt < 4; ++nt)
        #pragma unroll
        for (int e = 0; e < 4; ++e) acc[nt][e] = 0.f;

    #pragma unroll
    for (int ks = 0; ks < 8; ++ks) {
        uint32_t a[4];
        {   // A[m=d][k=j] from K[j][d] via trans
            const uint32_t arow = ks*16 + (lane & 7) + ((lane & 16) >> 1);
            LDSM4T(a, skb + arow*144 + (m0 + (lane & 8))*2);
        }
        #pragma unroll
        for (int p = 0; p < 2; ++p) {
            uint32_t t[4];
            const uint32_t baddr = svb + (ks*16 + (lane & 15))*144
                                 + (e0 + p*16 + (lane >> 4)*8)*2;
            LDSM4T(t, baddr);
            uint32_t b0[2] = { t[0], t[1] };
            uint32_t b1[2] = { t[2], t[3] };
            MMA_F16(acc[2*p],     a, b0);
            MMA_F16(acc[2*p + 1], a, b1);
        }
    }

    const int qr = lane >> 2, qc = (lane & 3)*2;
    float* outp = ckv + (((size_t)bh*NCHUNK + c) << 12);
    #pragma unroll
    for (int nt = 0; nt < 4; ++nt) {
        const int e = e0 + nt*8 + qc;
        const int d0 = m0 + qr, d1 = d0 + 8;
        float2 p0; p0.x = acc[nt][0]; p0.y = acc[nt][1];
        float2 p1; p1.x = acc[nt][2]; p1.y = acc[nt][3];
        *(float2*)&outp[d0*64 + e] = p0;
        *(float2*)&outp[d1*64 + e] = p1;
    }

    // ksum: cks[d] = sum_j K[j][d] (threads 0..63, each 2 j-halves)
    if (tid < 128) {
        const int dcol = tid & 63, jh = tid >> 6;      // jh in {0,1}
        float s = 0.f;
        #pragma unroll 16
        for (int j = jh*64; j < jh*64 + 64; ++j)
            s += __half2float(*(const __half*)(sk + j*144 + dcol*2));
        // combine the two halves via shared
        __shared__ float part[128];
        part[tid] = s;
        __syncthreads();
        if (tid < 64)
            cks[(bh*NCHUNK + c)*64 + tid] = part[tid] + part[tid + 64];
    }
}

// ---------------------------------------------------------------------------
// Exclusive prefix over chunks — St out as fp16. grid (NBH, 16), 256 threads.
// ---------------------------------------------------------------------------
__global__ __launch_bounds__(256) void prefix_kernel(
    const float* __restrict__ ckv, const float* __restrict__ cks,
    __half* __restrict__ pkv, float* __restrict__ pks)
{
    const int bh  = blockIdx.x;
    const int idx = blockIdx.y*256 + threadIdx.x;
    const size_t base = ((size_t)bh*NCHUNK) << 12;

    float v[NCHUNK];
    #pragma unroll
    for (int c = 0; c < NCHUNK; ++c) v[c] = ckv[base + ((size_t)c << 12) + idx];
    float acc = 0.f;
    #pragma unroll
    for (int c = 0; c < NCHUNK; ++c) {
        pkv[base + ((size_t)c << 12) + idx] = __float2half_rn(acc);
        acc += v[c];
    }
    if (blockIdx.y == 0 && threadIdx.x < 64) {
        const int t = threadIdx.x;
        float s[NCHUNK];
        #pragma unroll
        for (int c = 0; c < NCHUNK; ++c) s[c] = cks[(bh*NCHUNK + c)*64 + t];
        float a = 0.f;
        #pragma unroll
        for (int c = 0; c < NCHUNK; ++c) {
            pks[(bh*NCHUNK + c)*64 + t] = a;
            a += s[c];
        }
    }
}

// ---------------------------------------------------------------------------
// Tensor-core chunked linear attention, fp16. grid (NCHUNK, NBH), 256 thr.
// ---------------------------------------------------------------------------
#define A_Q    0u
#define A_K    18432u
#define A_V    36864u
#define A_ST   55296u
#define A_SC   64512u
#define A_KP   99328u
#define A_DLOC 99584u
#define ATTN_SMEM_BYTES 100096

__global__ __launch_bounds__(256, 2) void attn_kernel(
    const __half* __restrict__ Q16, const __half* __restrict__ K16,
    const __half* __restrict__ V16, const __half* __restrict__ pkv,
    const float* __restrict__ pks, __half* __restrict__ AV)
{
    extern __shared__ char sm[];
    const uint32_t smb = smem_u32(sm);

    const int c  = blockIdx.x, bh = blockIdx.y;
    const int b  = bh >> 3, hh = bh & 7;
    const int tid = threadIdx.x;
    const int wid = tid >> 5, lane = tid & 31;
    const int warp_m = wid >> 2, warp_n = wid & 3;

    {
        const __half2* Q2 = (const __half2*)Q16;
        const __half2* K2 = (const __half2*)K16;
        const __half2* V2 = (const __half2*)V16;
        #pragma unroll
        for (int t = 0; t < 16; ++t) {
            const int u = tid + t*256;
            const int row = u >> 5, c2 = u & 31;
            const size_t g = (size_t)((c*CHUNK + row)*BATCH + b)*256 + hh*32 + c2;
            const uint32_t so = row*144 + c2*4;
            *(__half2*)(sm + A_Q + so) = Q2[g];
            *(__half2*)(sm + A_K + so) = K2[g];
            *(__half2*)(sm + A_V + so) = V2[g];
        }
        const __half2* S2 = (const __half2*)pkv;
        const size_t sbase = ((size_t)(bh*NCHUNK + c))*2048;
        #pragma unroll
        for (int t = 0; t < 8; ++t) {
            const int u = tid + t*256;
            const int dd = u >> 5, e2 = u & 31;
            *(__half2*)(sm + A_ST + dd*144 + e2*4) = S2[sbase + u];
        }
        if (tid < 64)
            ((float*)(sm + A_KP))[tid] = pks[(bh*NCHUNK + c)*64 + tid];
    }
    __syncthreads();

    const int qr = lane >> 2, qc = (lane & 3)*2;

    // ---- Stage 1: S = Q @ K^T, masked -> Ssc fp16 ----
    {
        float d1[4][4][4];
        #pragma unroll
        for (int mt = 0; mt < 4; ++mt)
            #pragma unroll
            for (int nt = 0; nt < 4; ++nt)
                #pragma unroll
                for (int e = 0; e < 4; ++e) d1[mt][nt][e] = 0.f;

        #pragma unroll
        for (int ks = 0; ks < 4; ++ks) {
            uint32_t a[4][4];
            #pragma unroll
            for (int mt = 0; mt < 4; ++mt) {
                const uint32_t r = warp_m*64 + mt*16 + (lane & 15);
                LDSM4(a[mt], smb + A_Q + r*144 + ks*32 + (lane >> 4)*16);
            }
            uint32_t bf[4][2];
            #pragma unroll
            for (int p = 0; p < 2; ++p) {
                const uint32_t r = warp_n*32 + p*16 + (lane & 7) + ((lane & 16) >> 1);
                uint32_t t[4];
                LDSM4(t, smb + A_K + r*144 + ks*32 + (lane & 8)*2);
                bf[2*p][0]=t[0]; bf[2*p][1]=t[1]; bf[2*p+1][0]=t[2]; bf[2*p+1][1]=t[3];
            }
            #pragma unroll
            for (int mt = 0; mt < 4; ++mt)
                #pragma unroll
                for (int nt = 0; nt < 4; ++nt)
                    MMA_F16(d1[mt][nt], a[mt], bf[nt]);
        }
        #pragma unroll
        for (int mt = 0; mt < 4; ++mt) {
            const int i0 = warp_m*64 + mt*16 + qr, i1 = i0 + 8;
            #pragma unroll
            for (int nt = 0; nt < 4; ++nt) {
                const int j = warp_n*32 + nt*8 + qc;
                float v0 = (j   <= i0) ? d1[mt][nt][0] : 0.f;
                float v1 = (j+1 <= i0) ? d1[mt][nt][1] : 0.f;
                float v2 = (j   <= i1) ? d1[mt][nt][2] : 0.f;
                float v3 = (j+1 <= i1) ? d1[mt][nt][3] : 0.f;
                __half2 p0; p0.x = __float2half_rn(v0); p0.y = __float2half_rn(v1);
                __half2 p1; p1.x = __float2half_rn(v2); p1.y = __float2half_rn(v3);
                *(__half2*)(sm + A_SC + i0*272 + j*2) = p0;
                *(__half2*)(sm + A_SC + i1*272 + j*2) = p1;
            }
        }
    }
    __syncthreads();

    // ---- Stage 2: denominators ----
    {
        const int i = tid >> 1, half_ = tid & 1;
        float s = 0.f;
        const char* rh = sm + A_SC + i*272 + half_*128;
        #pragma unroll
        for (int j2 = 0; j2 < 32; ++j2) {
            __half2 ph = *(const __half2*)(rh + j2*4);
            s += __half2float(ph.x) + __half2float(ph.y);
        }
        const float* kp = (const float*)(sm + A_KP);
        const char* qh = sm + A_Q + i*144 + half_*64;
        #pragma unroll
        for (int k2 = 0; k2 < 16; ++k2) {
            __half2 ph = *(const __half2*)(qh + k2*4);
            const int k = half_*32 + k2*2;
            s = fmaf(__half2float(ph.x), kp[k],   s);
            s = fmaf(__half2float(ph.y), kp[k+1], s);
        }
        s += __shfl_xor_sync(0xffffffffu, s, 1);
        if (half_ == 0)
            ((float*)(sm + A_DLOC))[i] = 1.f / (s*ATT_SCALE + ATT_EPS);
    }
    __syncthreads();

    // ---- Stage 3: O = Ssc @ V + Q @ St ----
    {
        float d3[4][2][4];
        #pragma unroll
        for (int mt = 0; mt < 4; ++mt)
            #pragma unroll
            for (int nt = 0; nt < 2; ++nt)
                #pragma unroll
                for (int e = 0; e < 4; ++e) d3[mt][nt][e] = 0.f;

        #pragma unroll
        for (int ks = 0; ks < 8; ++ks) {
            uint32_t a[4][4];
            #pragma unroll
            for (int mt = 0; mt < 4; ++mt) {
                const uint32_t r = warp_m*64 + mt*16 + (lane & 15);
                LDSM4(a[mt], smb + A_SC + r*272 + ks*32 + (lane >> 4)*16);
            }
            uint32_t bf[2][2];
            {
                const uint32_t addr = smb + A_V + (ks*16 + (lane & 15))*144
                                    + (warp_n*16 + (lane >> 4)*8)*2;
                uint32_t t[4];
                LDSM4T(t, addr);
                bf[0][0]=t[0]; bf[0][1]=t[1]; bf[1][0]=t[2]; bf[1][1]=t[3];
            }
            #pragma unroll
            for (int mt = 0; mt < 4; ++mt)
                #pragma unroll
                for (int nt = 0; nt < 2; ++nt)
                    MMA_F16(d3[mt][nt], a[mt], bf[nt]);
        }
        #pragma unroll
        for (int ks = 0; ks < 4; ++ks) {
            uint32_t a[4][4];
            #pragma unroll
            for (int mt = 0; mt < 4; ++mt) {
                const uint32_t r = warp_m*64 + mt*16 + (lane & 15);
                LDSM4(a[mt], smb + A_Q + r*144 + ks*32 + (lane >> 4)*16);
            }
            uint32_t bf[2][2];
            {
                const uint32_t addr = smb + A_ST + (ks*16 + (lane & 15))*144
                                    + (warp_n*16 + (lane >> 4)*8)*2;
                uint32_t t[4];
                LDSM4T(t, addr);
                bf[0][0]=t[0]; bf[0][1]=t[1]; bf[1][0]=t[2]; bf[1][1]=t[3];
            }
            #pragma unroll
            for (int mt = 0; mt < 4; ++mt)
                #pragma unroll
                for (int nt = 0; nt < 2; ++nt)
                    MMA_F16(d3[mt][nt], a[mt], bf[nt]);
        }

        const float* dloc = (const float*)(sm + A_DLOC);
        __half2* AV2 = (__half2*)AV;
        #pragma unroll
        for (int mt = 0; mt < 4; ++mt) {
            const int i0 = warp_m*64 + mt*16 + qr, i1 = i0 + 8;
            const float sc0 = ATT_SCALE * dloc[i0];
            const float sc1 = ATT_SCALE * dloc[i1];
            const size_t g0 = (size_t)((c*CHUNK + i0)*BATCH + b)*256 + hh*32;
            const size_t g1 = (size_t)((c*CHUNK + i1)*BATCH + b)*256 + hh*32;
            #pragma unroll
            for (int nt = 0; nt < 2; ++nt) {
                const int n = warp_n*16 + nt*8 + qc;
                __half2 p0, p1;
                p0.x = __float2half_rn(d3[mt][nt][0]*sc0);
                p0.y = __float2half_rn(d3[mt][nt][1]*sc0);
                p1.x = __float2half_rn(d3[mt][nt][2]*sc1);
                p1.y = __float2half_rn(d3[mt][nt][3]*sc1);
                AV2[g0 + (n >> 1)] = p0;
                AV2[g1 + (n >> 1)] = p1;
            }
        }
    }
}

// ---------------------------------------------------------------------------
// LayerNorm(h + attn_out). One block per row (512 cols), 128 threads.
// ---------------------------------------------------------------------------
__global__ __launch_bounds__(128) void ln_kernel(
    const float* __restrict__ h, const float* __restrict__ ao,
    const float* __restrict__ gamma, const float* __restrict__ beta,
    float* __restrict__ out)
{
    const int row = blockIdx.x;
    const int tid = threadIdx.x;
    __shared__ float red[4];

    const float* hp = h  + (size_t)row*512;
    const float* ap = ao + (size_t)row*512;
    float x[4];
    #pragma unroll
    for (int r = 0; r < 4; ++r) x[r] = hp[tid + r*128] + ap[tid + r*128];

    float s = (x[0] + x[1]) + (x[2] + x[3]);
    #pragma unroll
    for (int o = 16; o > 0; o >>= 1) s += __shfl_xor_sync(0xffffffffu, s, o);
    if ((tid & 31) == 0) red[tid >> 5] = s;
    __syncthreads();
    const float mu = (red[0] + red[1] + red[2] + red[3]) * (1.f/512.f);
    __syncthreads();

    float v = 0.f;
    #pragma unroll
    for (int r = 0; r < 4; ++r) { const float d = x[r] - mu; v = fmaf(d, d, v); }
    #pragma unroll
    for (int o = 16; o > 0; o >>= 1) v += __shfl_xor_sync(0xffffffffu, v, o);
    if ((tid & 31) == 0) red[tid >> 5] = v;
    __syncthreads();
    const float var  = (red[0] + red[1] + red[2] + red[3]) * (1.f/512.f);
    const float rstd = rsqrtf(var + LN_EPS);

    #pragma unroll
    for (int r = 0; r < 4; ++r) {
        const int col = tid + r*128;
        out[(size_t)row*512 + col] = (x[r] - mu)*rstd*gamma[col] + beta[col];
    }
}

// ---------------------------------------------------------------------------
extern "C" void kernel_launch(void* const* d_in, const int* in_sizes, int n_in,
                              void* d_out, int out_size)
{
    (void)in_sizes; (void)n_in; (void)out_size;
    const float* h     = (const float*)d_in[0];
    const float* Wq    = (const float*)d_in[1];
    const float* Wkv   = (const float*)d_in[2];
    const float* Wo    = (const float*)d_in[3];
    const float* gamma = (const float*)d_in[4];
    const float* beta  = (const float*)d_in[5];
    float* out = (float*)d_out;

    __half *h16, *wq16, *wkv16, *wo16, *Q16, *K16, *V16, *pkv, *AV;
    float *ckv, *cks, *pks, *AO;
    cudaGetSymbolAddress((void**)&h16,   g_h16);
    cudaGetSymbolAddress((void**)&wq16,  g_Wq16);
    cudaGetSymbolAddress((void**)&wkv16, g_Wkv16);
    cudaGetSymbolAddress((void**)&wo16,  g_Wo16);
    cudaGetSymbolAddress((void**)&Q16,   g_Q);
    cudaGetSymbolAddress((void**)&K16,   g_K);
    cudaGetSymbolAddress((void**)&V16,   g_V);
    cudaGetSymbolAddress((void**)&ckv,   g_ckv);
    cudaGetSymbolAddress((void**)&cks,   g_cks);
    cudaGetSymbolAddress((void**)&pkv,   g_pkv);
    cudaGetSymbolAddress((void**)&pks,   g_pks);
    cudaGetSymbolAddress((void**)&AV,    g_AV);
    cudaGetSymbolAddress((void**)&AO,    g_AO);

    constexpr int GEMM_SMEM = 3 * (128*80 + 32*272);   // 56832

    cudaFuncSetAttribute(qkv_gemm,    cudaFuncAttributeMaxDynamicSharedMemorySize, GEMM_SMEM);
    cudaFuncSetAttribute(wo_gemm,     cudaFuncAttributeMaxDynamicSharedMemorySize, GEMM_SMEM);
    cudaFuncSetAttribute(attn_kernel, cudaFuncAttributeMaxDynamicSharedMemorySize, ATTN_SMEM_BYTES);

    convert_all_kernel<<<3072, 256>>>(h, Wq, Wkv, Wo, h16, wq16, wkv16, wo16);

    // merged Q + KV projections (one launch, 384 CTAs)
    qkv_gemm<<<dim3(12, 32), 256, GEMM_SMEM>>>(h16, wq16, wkv16, Q16, K16, V16);

    chunk_kv_kernel<<<dim3(NCHUNK, NBH), 256>>>(K16, V16, ckv, cks);
    prefix_kernel<<<dim3(NBH, 16), 256>>>(ckv, cks, pkv, pks);
    attn_kernel<<<dim3(NCHUNK, NBH), 256, ATTN_SMEM_BYTES>>>(Q16, K16, V16, pkv, pks, AV);

    wo_gemm<<<dim3(4, 32), 256, GEMM_SMEM>>>(AV, wo16, AO);

    ln_kernel<<<NROWS, 128>>>(h, AO, gamma, beta, out);
}